// round 5
// baseline (speedup 1.0000x reference)
#include <cuda_runtime.h>
#include <cuda_bf16.h>
#include <math.h>

// ---------------------------------------------------------------------------
// Problem constants
// ---------------------------------------------------------------------------
#define BB   8
#define NN   1374
#define CC   768
#define HH   12
#define HD   64
#define C3   2304
#define HID  3072
#define MM   (BB * NN)          // 10992 rows
#define LN_EPS 1e-5f

// ---------------------------------------------------------------------------
// Scratch (device globals; no allocations allowed)
// ---------------------------------------------------------------------------
__device__ float g_h[MM * CC];        // LN output (reused for LN1 and LN2)
__device__ float g_qkv[MM * C3];      // QKV output (RoPE applied in place)
__device__ float g_attn[MM * CC];     // attention output, [B,N,H*HD] layout
__device__ float g_x1[MM * HID];      // MLP x1 -> hid
__device__ float g_x2[MM * HID];      // MLP x2

// ---------------------------------------------------------------------------
// LayerNorm: one block (256 threads) per row of 768
// ---------------------------------------------------------------------------
__global__ void ln_kernel(const float* __restrict__ x,
                          const float* __restrict__ g,
                          const float* __restrict__ b,
                          float* __restrict__ out)
{
    int row = blockIdx.x;
    int tid = threadIdx.x;
    int lane = tid & 31;
    int wid  = tid >> 5;
    const float* xr = x + (size_t)row * CC;

    float v0 = xr[tid];
    float v1 = xr[tid + 256];
    float v2 = xr[tid + 512];

    __shared__ float red[8];

    // mean
    float s = v0 + v1 + v2;
    #pragma unroll
    for (int off = 16; off > 0; off >>= 1) s += __shfl_xor_sync(0xffffffffu, s, off);
    if (lane == 0) red[wid] = s;
    __syncthreads();
    float tot = red[0] + red[1] + red[2] + red[3] + red[4] + red[5] + red[6] + red[7];
    float mean = tot * (1.0f / (float)CC);
    __syncthreads();

    // variance
    float d0 = v0 - mean, d1 = v1 - mean, d2 = v2 - mean;
    float sq = d0 * d0 + d1 * d1 + d2 * d2;
    #pragma unroll
    for (int off = 16; off > 0; off >>= 1) sq += __shfl_xor_sync(0xffffffffu, sq, off);
    if (lane == 0) red[wid] = sq;
    __syncthreads();
    float tot2 = red[0] + red[1] + red[2] + red[3] + red[4] + red[5] + red[6] + red[7];
    float var = tot2 * (1.0f / (float)CC);
    float rstd = rsqrtf(var + LN_EPS);

    float* orow = out + (size_t)row * CC;
    orow[tid]       = d0 * rstd * g[tid]       + b[tid];
    orow[tid + 256] = d1 * rstd * g[tid + 256] + b[tid + 256];
    orow[tid + 512] = d2 * rstd * g[tid + 512] + b[tid + 512];
}

// ---------------------------------------------------------------------------
// Tiled fp32 NT GEMM: out[m,n] = sum_k A[m,k]*W[n,k] + bias[n] (+ R[m,n])
// BM=BN=128, BK=16, 256 threads, 8x8 micro-tile per thread.
// N and K assumed multiples of 128/16; M guarded.
// ---------------------------------------------------------------------------
template <bool RES>
__global__ void __launch_bounds__(256, 2)
gemm_nt(const float* __restrict__ A, const float* __restrict__ W,
        const float* __restrict__ bias, const float* __restrict__ R,
        float* __restrict__ out, int M, int N, int K)
{
    __shared__ float As[16][132];
    __shared__ float Ws[16][132];

    int tid = threadIdx.x;
    int tx = tid & 15;        // 0..15 -> N micro dim
    int ty = tid >> 4;        // 0..15 -> M micro dim
    int m0 = blockIdx.y * 128;
    int n0 = blockIdx.x * 128;

    int ar = tid >> 2;        // 0..63  (row within half-tile for loads)
    int ac = tid & 3;         // float4 slot along K (BK=16 -> 4 slots)

    float acc[8][8];
    #pragma unroll
    for (int i = 0; i < 8; i++)
        #pragma unroll
        for (int j = 0; j < 8; j++) acc[i][j] = 0.0f;

    for (int k0 = 0; k0 < K; k0 += 16) {
        // load A tile (transposed into As[k][m]); guard M edge
        #pragma unroll
        for (int i = 0; i < 2; i++) {
            int r = ar + i * 64;
            int gm = m0 + r;
            float4 v = make_float4(0.f, 0.f, 0.f, 0.f);
            if (gm < M) v = *(const float4*)&A[(size_t)gm * K + k0 + ac * 4];
            As[ac * 4 + 0][r] = v.x;
            As[ac * 4 + 1][r] = v.y;
            As[ac * 4 + 2][r] = v.z;
            As[ac * 4 + 3][r] = v.w;
        }
        // load W tile (transposed into Ws[k][n]); N always full tiles
        #pragma unroll
        for (int i = 0; i < 2; i++) {
            int r = ar + i * 64;
            float4 v = *(const float4*)&W[(size_t)(n0 + r) * K + k0 + ac * 4];
            Ws[ac * 4 + 0][r] = v.x;
            Ws[ac * 4 + 1][r] = v.y;
            Ws[ac * 4 + 2][r] = v.z;
            Ws[ac * 4 + 3][r] = v.w;
        }
        __syncthreads();

        #pragma unroll
        for (int k = 0; k < 16; k++) {
            float a[8], w[8];
            *(float4*)(a)     = *(const float4*)&As[k][ty * 8];
            *(float4*)(a + 4) = *(const float4*)&As[k][ty * 8 + 4];
            *(float4*)(w)     = *(const float4*)&Ws[k][tx * 8];
            *(float4*)(w + 4) = *(const float4*)&Ws[k][tx * 8 + 4];
            #pragma unroll
            for (int i = 0; i < 8; i++)
                #pragma unroll
                for (int j = 0; j < 8; j++)
                    acc[i][j] = fmaf(a[i], w[j], acc[i][j]);
        }
        __syncthreads();
    }

    // epilogue
    #pragma unroll
    for (int i = 0; i < 8; i++) {
        int gm = m0 + ty * 8 + i;
        if (gm >= M) continue;
        #pragma unroll
        for (int j4 = 0; j4 < 2; j4++) {
            int gn = n0 + tx * 8 + j4 * 4;
            float4 b4 = *(const float4*)&bias[gn];
            float4 o;
            o.x = acc[i][j4 * 4 + 0] + b4.x;
            o.y = acc[i][j4 * 4 + 1] + b4.y;
            o.z = acc[i][j4 * 4 + 2] + b4.z;
            o.w = acc[i][j4 * 4 + 3] + b4.w;
            if (RES) {
                float4 r4 = *(const float4*)&R[(size_t)gm * N + gn];
                o.x += r4.x; o.y += r4.y; o.z += r4.z; o.w += r4.w;
            }
            *(float4*)&out[(size_t)gm * N + gn] = o;
        }
    }
}

// ---------------------------------------------------------------------------
// RoPE applied in place to q and k halves of g_qkv.
// qkv row layout per token: [3, H, HD]; freqs: [N, HD].
// ---------------------------------------------------------------------------
__global__ void rope_kernel(float* __restrict__ qkv,
                            const float* __restrict__ freqs)
{
    int idx = blockIdx.x * blockDim.x + threadIdx.x;
    if (idx >= MM * 768) return;           // M * 2(q,k) * H * 32 pairs
    int m   = idx / 768;
    int rem = idx % 768;
    int s   = rem / 384;                   // 0 = q, 1 = k
    int hr  = rem % 384;
    int h   = hr >> 5;
    int dd  = hr & 31;
    int n   = m % NN;

    size_t base = (size_t)m * C3 + s * CC + h * HD;
    float f1 = freqs[n * HD + dd];
    float f2 = freqs[n * HD + dd + 32];
    float c1, s1, c2, s2;
    sincosf(f1, &s1, &c1);
    sincosf(f2, &s2, &c2);
    float x1 = qkv[base + dd];
    float x2 = qkv[base + dd + 32];
    qkv[base + dd]      = x1 * c1 - x2 * s1;
    qkv[base + dd + 32] = x2 * c2 + x1 * s2;
}

// ---------------------------------------------------------------------------
// Flash attention (fp32). BQ = BKV = 64, 256 threads (16x16 grid, 4x4 tiles).
// Q/K stored d-major in smem; V kv-major; S/P share one smem buffer.
// Output: g_attn[(b*N+n)*768 + h*64 + d].
// ---------------------------------------------------------------------------
__global__ void __launch_bounds__(256)
flash_attn_kernel(const float* __restrict__ qkv, float* __restrict__ o)
{
    extern __shared__ float sm[];
    float* Qt    = sm;                  // [64][64], index d*64 + q
    float* Kt    = sm + 4096;           // [64][64], index d*64 + kv
    float* Vs    = sm + 8192;           // [64][64], index kv*64 + d
    float* Ss    = sm + 12288;          // [64][64], S then P-transposed
    float* row_m = sm + 16384;          // [64]
    float* row_l = row_m + 64;          // [64]
    float* row_s = row_l + 64;          // [64]

    int tid = threadIdx.x;
    int tx = tid & 15;                  // output-d micro (4 cols)
    int ty = tid >> 4;                  // query micro (4 rows)
    int q0 = blockIdx.x * 64;
    int bh = blockIdx.y;
    int b  = bh / HH;
    int h  = bh % HH;
    size_t headoff = (size_t)h * HD;

    if (tid < 64) { row_m[tid] = -INFINITY; row_l[tid] = 0.0f; }

    // load Q tile (transposed: Qt[d][q])
    #pragma unroll
    for (int i = 0; i < 4; i++) {
        int idx = tid + i * 256;
        int r = idx >> 4;               // query row 0..63
        int c4 = idx & 15;              // float4 along d
        int n = q0 + r;
        float4 v = make_float4(0.f, 0.f, 0.f, 0.f);
        if (n < NN) v = *(const float4*)&qkv[(size_t)(b * NN + n) * C3 + headoff + c4 * 4];
        int d = c4 * 4;
        Qt[(d + 0) * 64 + r] = v.x;
        Qt[(d + 1) * 64 + r] = v.y;
        Qt[(d + 2) * 64 + r] = v.z;
        Qt[(d + 3) * 64 + r] = v.w;
    }

    float acc[4][4];
    #pragma unroll
    for (int i = 0; i < 4; i++)
        #pragma unroll
        for (int j = 0; j < 4; j++) acc[i][j] = 0.0f;

    const float scale = 0.125f;         // 64^-0.5
    const int ntiles = (NN + 63) / 64;  // 22

    for (int t = 0; t < ntiles; t++) {
        int kv0 = t * 64;
        __syncthreads();                // protect Kt/Vs/Ss vs previous iter reads

        // load K (transposed) and V (direct)
        #pragma unroll
        for (int i = 0; i < 4; i++) {
            int idx = tid + i * 256;
            int r = idx >> 4;
            int c4 = idx & 15;
            int n = kv0 + r;
            float4 kv = make_float4(0.f, 0.f, 0.f, 0.f);
            float4 vv = make_float4(0.f, 0.f, 0.f, 0.f);
            if (n < NN) {
                size_t base = (size_t)(b * NN + n) * C3 + headoff;
                kv = *(const float4*)&qkv[base + CC + c4 * 4];
                vv = *(const float4*)&qkv[base + 2 * CC + c4 * 4];
            }
            int d = c4 * 4;
            Kt[(d + 0) * 64 + r] = kv.x;
            Kt[(d + 1) * 64 + r] = kv.y;
            Kt[(d + 2) * 64 + r] = kv.z;
            Kt[(d + 3) * 64 + r] = kv.w;
            *(float4*)&Vs[r * 64 + d] = vv;
        }
        __syncthreads();

        // S = Q K^T  (4x4 per thread)
        float s[4][4];
        #pragma unroll
        for (int i = 0; i < 4; i++)
            #pragma unroll
            for (int j = 0; j < 4; j++) s[i][j] = 0.0f;
        #pragma unroll 8
        for (int d = 0; d < 64; d++) {
            float4 qa = *(const float4*)&Qt[d * 64 + ty * 4];
            float4 kb = *(const float4*)&Kt[d * 64 + tx * 4];
            float qq[4] = {qa.x, qa.y, qa.z, qa.w};
            float kk[4] = {kb.x, kb.y, kb.z, kb.w};
            #pragma unroll
            for (int i = 0; i < 4; i++)
                #pragma unroll
                for (int j = 0; j < 4; j++)
                    s[i][j] = fmaf(qq[i], kk[j], s[i][j]);
        }
        // scale + key mask, write S
        #pragma unroll
        for (int i = 0; i < 4; i++)
            #pragma unroll
            for (int j = 0; j < 4; j++) {
                int c = kv0 + tx * 4 + j;
                Ss[(ty * 4 + i) * 64 + tx * 4 + j] =
                    (c < NN) ? s[i][j] * scale : -INFINITY;
            }
        __syncthreads();

        // online softmax: 4 lanes per row, 16 cols each
        {
            int r = tid >> 2;
            int part = tid & 3;
            float pv[16];
            #pragma unroll
            for (int j4 = 0; j4 < 4; j4++)
                *(float4*)&pv[j4 * 4] = *(const float4*)&Ss[r * 64 + part * 16 + j4 * 4];
            float lmax = pv[0];
            #pragma unroll
            for (int j = 1; j < 16; j++) lmax = fmaxf(lmax, pv[j]);
            lmax = fmaxf(lmax, __shfl_xor_sync(0xffffffffu, lmax, 1));
            lmax = fmaxf(lmax, __shfl_xor_sync(0xffffffffu, lmax, 2));
            float m_old = row_m[r];
            float m_new = fmaxf(m_old, lmax);
            float lsum = 0.0f;
            #pragma unroll
            for (int j = 0; j < 16; j++) {
                pv[j] = __expf(pv[j] - m_new);   // exp(-inf)=0 handles mask
                lsum += pv[j];
            }
            lsum += __shfl_xor_sync(0xffffffffu, lsum, 1);
            lsum += __shfl_xor_sync(0xffffffffu, lsum, 2);
            float sc = __expf(m_old - m_new);    // m_old=-inf -> 0
            if (part == 0) {
                row_s[r] = sc;
                row_m[r] = m_new;
                row_l[r] = row_l[r] * sc + lsum;
            }
            __syncthreads();                     // all S reads done
            // write P transposed: Ss[c][r]
            #pragma unroll
            for (int j = 0; j < 16; j++)
                Ss[(part * 16 + j) * 64 + r] = pv[j];
        }
        __syncthreads();

        // rescale O and accumulate P @ V
        float rs[4];
        #pragma unroll
        for (int i = 0; i < 4; i++) rs[i] = row_s[ty * 4 + i];
        #pragma unroll
        for (int i = 0; i < 4; i++)
            #pragma unroll
            for (int j = 0; j < 4; j++) acc[i][j] *= rs[i];
        #pragma unroll 8
        for (int kk2 = 0; kk2 < 64; kk2++) {
            float4 pa = *(const float4*)&Ss[kk2 * 64 + ty * 4];
            float4 vb = *(const float4*)&Vs[kk2 * 64 + tx * 4];
            float pp[4] = {pa.x, pa.y, pa.z, pa.w};
            float vv[4] = {vb.x, vb.y, vb.z, vb.w};
            #pragma unroll
            for (int i = 0; i < 4; i++)
                #pragma unroll
                for (int j = 0; j < 4; j++)
                    acc[i][j] = fmaf(pp[i], vv[j], acc[i][j]);
        }
    }

    // normalize + store
    #pragma unroll
    for (int i = 0; i < 4; i++) {
        int n = q0 + ty * 4 + i;
        if (n >= NN) continue;
        float inv = 1.0f / row_l[ty * 4 + i];
        float4 ov;
        ov.x = acc[i][0] * inv;
        ov.y = acc[i][1] * inv;
        ov.z = acc[i][2] * inv;
        ov.w = acc[i][3] * inv;
        *(float4*)&o[(size_t)(b * NN + n) * CC + headoff + tx * 4] = ov;
    }
}

// ---------------------------------------------------------------------------
// SwiGLU gate: hid = silu(x1) * x2  (in place into x1), float4
// ---------------------------------------------------------------------------
__global__ void silu_kernel(float* __restrict__ x1, const float* __restrict__ x2)
{
    int idx = blockIdx.x * blockDim.x + threadIdx.x;
    int total4 = MM * HID / 4;
    if (idx >= total4) return;
    float4 a = ((const float4*)x1)[idx];
    float4 b = ((const float4*)x2)[idx];
    a.x = a.x / (1.0f + __expf(-a.x)) * b.x;
    a.y = a.y / (1.0f + __expf(-a.y)) * b.y;
    a.z = a.z / (1.0f + __expf(-a.z)) * b.z;
    a.w = a.w / (1.0f + __expf(-a.w)) * b.w;
    ((float4*)x1)[idx] = a;
}

// ---------------------------------------------------------------------------
// Launch
// ---------------------------------------------------------------------------
extern "C" void kernel_launch(void* const* d_in, const int* in_sizes, int n_in,
                              void* d_out, int out_size)
{
    const float* x      = (const float*)d_in[0];
    const float* freqs  = (const float*)d_in[1];
    const float* ln1_g  = (const float*)d_in[2];
    const float* ln1_b  = (const float*)d_in[3];
    const float* qkv_w  = (const float*)d_in[4];
    const float* qkv_b  = (const float*)d_in[5];
    const float* proj_w = (const float*)d_in[6];
    const float* proj_b = (const float*)d_in[7];
    const float* ln2_g  = (const float*)d_in[8];
    const float* ln2_b  = (const float*)d_in[9];
    const float* w1     = (const float*)d_in[10];
    const float* b1     = (const float*)d_in[11];
    const float* w2     = (const float*)d_in[12];
    const float* b2     = (const float*)d_in[13];
    const float* w3     = (const float*)d_in[14];
    const float* b3     = (const float*)d_in[15];
    float* out = (float*)d_out;

    float *h_buf, *qkv_buf, *attn_buf, *x1_buf, *x2_buf;
    cudaGetSymbolAddress((void**)&h_buf, g_h);
    cudaGetSymbolAddress((void**)&qkv_buf, g_qkv);
    cudaGetSymbolAddress((void**)&attn_buf, g_attn);
    cudaGetSymbolAddress((void**)&x1_buf, g_x1);
    cudaGetSymbolAddress((void**)&x2_buf, g_x2);

    const int mblocks = (MM + 127) / 128;   // 86

    // 1) LN1
    ln_kernel<<<MM, 256>>>(x, ln1_g, ln1_b, h_buf);

    // 2) QKV GEMM: [M,768] x [2304,768]^T
    gemm_nt<false><<<dim3(C3 / 128, mblocks), 256>>>(
        h_buf, qkv_w, qkv_b, nullptr, qkv_buf, MM, C3, CC);

    // 3) RoPE in place
    {
        int total = MM * 768;
        rope_kernel<<<(total + 255) / 256, 256>>>(qkv_buf, freqs);
    }

    // 4) Flash attention
    {
        int smem = (4 * 64 * 64 + 3 * 64) * (int)sizeof(float);  // 66304
        cudaFuncSetAttribute(flash_attn_kernel,
                             cudaFuncAttributeMaxDynamicSharedMemorySize, smem);
        dim3 grid((NN + 63) / 64, BB * HH);   // (22, 96)
        flash_attn_kernel<<<grid, 256, smem>>>(qkv_buf, attn_buf);
    }

    // 5) proj GEMM + residual(x) -> out (holds x_res)
    gemm_nt<true><<<dim3(CC / 128, mblocks), 256>>>(
        attn_buf, proj_w, proj_b, x, out, MM, CC, CC);

    // 6) LN2
    ln_kernel<<<MM, 256>>>(out, ln2_g, ln2_b, h_buf);

    // 7) x1 = h @ w1^T + b1 ; 8) x2 = h @ w2^T + b2
    gemm_nt<false><<<dim3(HID / 128, mblocks), 256>>>(
        h_buf, w1, b1, nullptr, x1_buf, MM, HID, CC);
    gemm_nt<false><<<dim3(HID / 128, mblocks), 256>>>(
        h_buf, w2, b2, nullptr, x2_buf, MM, HID, CC);

    // 9) hid = silu(x1) * x2 (in place into x1)
    {
        int total4 = MM * HID / 4;
        silu_kernel<<<(total4 + 255) / 256, 256>>>(x1_buf, x2_buf);
    }

    // 10) mlp GEMM + residual(out) -> out
    gemm_nt<true><<<dim3(CC / 128, mblocks), 256>>>(
        x1_buf, w3, b3, out, out, MM, CC, HID);
}

// round 9
// speedup vs baseline: 1.9457x; 1.9457x over previous
#include <cuda_runtime.h>
#include <cuda_bf16.h>
#include <math.h>
#include <stdint.h>

// ---------------------------------------------------------------------------
// Problem constants
// ---------------------------------------------------------------------------
#define BB   8
#define NN   1374
#define CC   768
#define HH   12
#define HD   64
#define C3   2304
#define HID  3072
#define MM   (BB * NN)          // 10992 rows
#define LN_EPS 1e-5f

// ---------------------------------------------------------------------------
// Scratch (device globals; no allocations allowed)
// ---------------------------------------------------------------------------
__device__ float g_h[MM * CC];          // LN output (tf32-rounded)
__device__ float g_qkv[MM * C3];        // QKV output (RoPE in place, fp32)
__device__ float g_attn[MM * CC];       // attention output (tf32-rounded)
__device__ float g_x1[MM * HID];        // MLP x1 -> hid (tf32-rounded after silu)
__device__ float g_x2[MM * HID];        // MLP x2
// tf32-rounded weight copies: qkv(1769472) proj(589824) w1(2359296) w2(2359296) w3(2359296)
#define WR_QKV  0
#define WR_PROJ 1769472
#define WR_W1   2359296
#define WR_W2   4718592
#define WR_W3   7077888
#define WR_TOT  9437184
__device__ float g_wr[WR_TOT];

// ---------------------------------------------------------------------------
// Helpers
// ---------------------------------------------------------------------------
__device__ __forceinline__ float tf32r(float x) {
    uint32_t o, i = __float_as_uint(x);
    asm("cvt.rna.tf32.f32 %0, %1;" : "=r"(o) : "r"(i));
    return __uint_as_float(o);
}
__device__ __forceinline__ uint32_t smem_u32(const void* p) {
    uint32_t a;
    asm("{ .reg .u64 t; cvta.to.shared.u64 t, %1; cvt.u32.u64 %0, t; }"
        : "=r"(a) : "l"(p));
    return a;
}
__device__ __forceinline__ void cp_async16(uint32_t dst, const void* src, uint32_t sz) {
    asm volatile("cp.async.cg.shared.global [%0], [%1], 16, %2;"
                 :: "r"(dst), "l"(src), "r"(sz));
}
#define CP_COMMIT() asm volatile("cp.async.commit_group;" ::: "memory")
#define CP_WAIT1()  asm volatile("cp.async.wait_group 1;" ::: "memory")

__device__ __forceinline__ void mma_tf32(float* d, const uint32_t* a, const uint32_t* b) {
    asm volatile(
        "mma.sync.aligned.m16n8k8.row.col.f32.tf32.tf32.f32 "
        "{%0,%1,%2,%3}, {%4,%5,%6,%7}, {%8,%9}, {%0,%1,%2,%3};"
        : "+f"(d[0]), "+f"(d[1]), "+f"(d[2]), "+f"(d[3])
        : "r"(a[0]), "r"(a[1]), "r"(a[2]), "r"(a[3]), "r"(b[0]), "r"(b[1]));
}

// ---------------------------------------------------------------------------
// Round fp32 -> tf32 bit pattern (weights)
// ---------------------------------------------------------------------------
__global__ void round_tf32_kernel(const float* __restrict__ in,
                                  float* __restrict__ out, int n4)
{
    int idx = blockIdx.x * blockDim.x + threadIdx.x;
    if (idx >= n4) return;
    float4 v = ((const float4*)in)[idx];
    v.x = tf32r(v.x); v.y = tf32r(v.y); v.z = tf32r(v.z); v.w = tf32r(v.w);
    ((float4*)out)[idx] = v;
}

// ---------------------------------------------------------------------------
// tf32 tensor-core NT GEMM: out[m,n] = sum_k A[m,k]*W[n,k] + bias[n] (+R[m,n])
// A, W pre-rounded to tf32. BM=BN=128, BK=16, 8 warps (2x4), warp tile 64x32.
// 3-stage cp.async pipeline. smem rows padded to 20 floats (conflict-free).
// ---------------------------------------------------------------------------
#define GM_LDS  20
#define GM_ASTF (128 * GM_LDS)            // 2560 floats per A stage
#define GM_STF  (2 * GM_ASTF)             // 5120 floats per stage (A + B)
#define GM_SMEM (3 * GM_STF * 4)          // 61440 bytes

template <bool RES>
__global__ void __launch_bounds__(256, 2)
gemm_tf32(const float* __restrict__ A, const float* __restrict__ W,
          const float* __restrict__ bias, const float* R, float* __restrict__ out,
          int M, int N, int K)
{
    extern __shared__ float sm[];
    const uint32_t sb = smem_u32(sm);
    const int tid  = threadIdx.x;
    const int warp = tid >> 5;
    const int lane = tid & 31;
    const int wm = warp >> 2;            // 0..1
    const int wn = warp & 3;             // 0..3
    const int r = lane >> 2;             // 0..7
    const int c = lane & 3;              // 0..3
    const int m0 = blockIdx.y * 128;
    const int n0 = blockIdx.x * 128;

    const int row_l = tid >> 2;          // 0..63 (loader row, +64 for p=1)
    const int c4    = tid & 3;           // float4 slot along K

    float acc[4][4][4];
    #pragma unroll
    for (int i = 0; i < 4; i++)
        #pragma unroll
        for (int j = 0; j < 4; j++)
            #pragma unroll
            for (int e = 0; e < 4; e++) acc[i][j][e] = 0.0f;

    const int nchunk = K >> 4;

    auto load_stage = [&](int s, int ch) {
        const int k0 = ch << 4;
        const uint32_t sa = sb + (uint32_t)(s * GM_STF) * 4u;
        // A tile: 128 rows x 16 floats
        #pragma unroll
        for (int p = 0; p < 2; p++) {
            int row = row_l + p * 64;
            int gm = m0 + row;
            int gms = gm < M ? gm : M - 1;
            const float* src = A + (size_t)gms * K + k0 + c4 * 4;
            uint32_t dst = sa + (uint32_t)(row * GM_LDS + c4 * 4) * 4u;
            cp_async16(dst, src, gm < M ? 16u : 0u);
        }
        // B tile: 128 rows x 16 floats (N always multiple of 128)
        #pragma unroll
        for (int p = 0; p < 2; p++) {
            int row = row_l + p * 64;
            const float* src = W + (size_t)(n0 + row) * K + k0 + c4 * 4;
            uint32_t dst = sa + (uint32_t)(GM_ASTF + row * GM_LDS + c4 * 4) * 4u;
            cp_async16(dst, src, 16u);
        }
    };

    load_stage(0, 0); CP_COMMIT();
    load_stage(1, 1); CP_COMMIT();

    for (int ch = 0; ch < nchunk; ch++) {
        int s = ch % 3;
        CP_WAIT1();
        __syncthreads();
        if (ch + 2 < nchunk) load_stage((ch + 2) % 3, ch + 2);
        CP_COMMIT();

        const float* As = sm + s * GM_STF;
        const float* Bs = As + GM_ASTF;
        const float* ab = As + (wm * 64 + r) * GM_LDS + c;
        const float* bb = Bs + (wn * 32 + r) * GM_LDS + c;

        #pragma unroll
        for (int ks = 0; ks < 2; ks++) {
            uint32_t af[4][4], bf[4][2];
            #pragma unroll
            for (int i = 0; i < 4; i++) {
                const float* pa = ab + i * 16 * GM_LDS + ks * 8;
                af[i][0] = __float_as_uint(pa[0]);
                af[i][1] = __float_as_uint(pa[8 * GM_LDS]);
                af[i][2] = __float_as_uint(pa[4]);
                af[i][3] = __float_as_uint(pa[8 * GM_LDS + 4]);
            }
            #pragma unroll
            for (int j = 0; j < 4; j++) {
                const float* pb = bb + j * 8 * GM_LDS + ks * 8;
                bf[j][0] = __float_as_uint(pb[0]);
                bf[j][1] = __float_as_uint(pb[4]);
            }
            #pragma unroll
            for (int i = 0; i < 4; i++)
                #pragma unroll
                for (int j = 0; j < 4; j++)
                    mma_tf32(acc[i][j], af[i], bf[j]);
        }
    }

    // epilogue: thread element (r, 2c)/(r, 2c+1) and (r+8, ...)
    #pragma unroll
    for (int i = 0; i < 4; i++) {
        int gr0 = m0 + wm * 64 + i * 16 + r;
        int gr1 = gr0 + 8;
        #pragma unroll
        for (int j = 0; j < 4; j++) {
            int gn = n0 + wn * 32 + j * 8 + 2 * c;
            float2 b2 = *(const float2*)&bias[gn];
            if (gr0 < M) {
                float2 o;
                o.x = acc[i][j][0] + b2.x;
                o.y = acc[i][j][1] + b2.y;
                if (RES) {
                    float2 r2 = *(const float2*)&R[(size_t)gr0 * N + gn];
                    o.x += r2.x; o.y += r2.y;
                }
                *(float2*)&out[(size_t)gr0 * N + gn] = o;
            }
            if (gr1 < M) {
                float2 o;
                o.x = acc[i][j][2] + b2.x;
                o.y = acc[i][j][3] + b2.y;
                if (RES) {
                    float2 r2 = *(const float2*)&R[(size_t)gr1 * N + gn];
                    o.x += r2.x; o.y += r2.y;
                }
                *(float2*)&out[(size_t)gr1 * N + gn] = o;
            }
        }
    }
}

// ---------------------------------------------------------------------------
// LayerNorm: one block (256 threads) per row of 768. Output tf32-rounded
// (feeds GEMMs only).
// ---------------------------------------------------------------------------
__global__ void ln_kernel(const float* __restrict__ x,
                          const float* __restrict__ g,
                          const float* __restrict__ b,
                          float* __restrict__ out)
{
    int row = blockIdx.x;
    int tid = threadIdx.x;
    int lane = tid & 31;
    int wid  = tid >> 5;
    const float* xr = x + (size_t)row * CC;

    float v0 = xr[tid];
    float v1 = xr[tid + 256];
    float v2 = xr[tid + 512];

    __shared__ float red[8];

    float s = v0 + v1 + v2;
    #pragma unroll
    for (int off = 16; off > 0; off >>= 1) s += __shfl_xor_sync(0xffffffffu, s, off);
    if (lane == 0) red[wid] = s;
    __syncthreads();
    float tot = red[0] + red[1] + red[2] + red[3] + red[4] + red[5] + red[6] + red[7];
    float mean = tot * (1.0f / (float)CC);
    __syncthreads();

    float d0 = v0 - mean, d1 = v1 - mean, d2 = v2 - mean;
    float sq = d0 * d0 + d1 * d1 + d2 * d2;
    #pragma unroll
    for (int off = 16; off > 0; off >>= 1) sq += __shfl_xor_sync(0xffffffffu, sq, off);
    if (lane == 0) red[wid] = sq;
    __syncthreads();
    float tot2 = red[0] + red[1] + red[2] + red[3] + red[4] + red[5] + red[6] + red[7];
    float var = tot2 * (1.0f / (float)CC);
    float rstd = rsqrtf(var + LN_EPS);

    float* orow = out + (size_t)row * CC;
    orow[tid]       = tf32r(d0 * rstd * g[tid]       + b[tid]);
    orow[tid + 256] = tf32r(d1 * rstd * g[tid + 256] + b[tid + 256]);
    orow[tid + 512] = tf32r(d2 * rstd * g[tid + 512] + b[tid + 512]);
}

// ---------------------------------------------------------------------------
// RoPE in place on q,k halves of g_qkv. qkv row layout: [3, H, HD]; freqs [N,HD].
// ---------------------------------------------------------------------------
__global__ void rope_kernel(float* __restrict__ qkv,
                            const float* __restrict__ freqs)
{
    int idx = blockIdx.x * blockDim.x + threadIdx.x;
    if (idx >= MM * 768) return;
    int m   = idx / 768;
    int rem = idx % 768;
    int s   = rem / 384;
    int hr  = rem % 384;
    int h   = hr >> 5;
    int dd  = hr & 31;
    int n   = m % NN;

    size_t base = (size_t)m * C3 + s * CC + h * HD;
    float f1 = freqs[n * HD + dd];
    float f2 = freqs[n * HD + dd + 32];
    float c1, s1, c2, s2;
    sincosf(f1, &s1, &c1);
    sincosf(f2, &s2, &c2);
    float x1 = qkv[base + dd];
    float x2 = qkv[base + dd + 32];
    qkv[base + dd]      = x1 * c1 - x2 * s1;
    qkv[base + dd + 32] = x2 * c2 + x1 * s2;
}

// ---------------------------------------------------------------------------
// Flash attention (fp32). Output tf32-rounded (feeds proj GEMM only).
// ---------------------------------------------------------------------------
__global__ void __launch_bounds__(256)
flash_attn_kernel(const float* __restrict__ qkv, float* __restrict__ o)
{
    extern __shared__ float sm[];
    float* Qt    = sm;
    float* Kt    = sm + 4096;
    float* Vs    = sm + 8192;
    float* Ss    = sm + 12288;
    float* row_m = sm + 16384;
    float* row_l = row_m + 64;
    float* row_s = row_l + 64;

    int tid = threadIdx.x;
    int tx = tid & 15;
    int ty = tid >> 4;
    int q0 = blockIdx.x * 64;
    int bh = blockIdx.y;
    int b  = bh / HH;
    int h  = bh % HH;
    size_t headoff = (size_t)h * HD;

    if (tid < 64) { row_m[tid] = -INFINITY; row_l[tid] = 0.0f; }

    #pragma unroll
    for (int i = 0; i < 4; i++) {
        int idx = tid + i * 256;
        int r = idx >> 4;
        int c4 = idx & 15;
        int n = q0 + r;
        float4 v = make_float4(0.f, 0.f, 0.f, 0.f);
        if (n < NN) v = *(const float4*)&qkv[(size_t)(b * NN + n) * C3 + headoff + c4 * 4];
        int d = c4 * 4;
        Qt[(d + 0) * 64 + r] = v.x;
        Qt[(d + 1) * 64 + r] = v.y;
        Qt[(d + 2) * 64 + r] = v.z;
        Qt[(d + 3) * 64 + r] = v.w;
    }

    float acc[4][4];
    #pragma unroll
    for (int i = 0; i < 4; i++)
        #pragma unroll
        for (int j = 0; j < 4; j++) acc[i][j] = 0.0f;

    const float scale = 0.125f;
    const int ntiles = (NN + 63) / 64;

    for (int t = 0; t < ntiles; t++) {
        int kv0 = t * 64;
        __syncthreads();

        #pragma unroll
        for (int i = 0; i < 4; i++) {
            int idx = tid + i * 256;
            int r = idx >> 4;
            int c4 = idx & 15;
            int n = kv0 + r;
            float4 kv = make_float4(0.f, 0.f, 0.f, 0.f);
            float4 vv = make_float4(0.f, 0.f, 0.f, 0.f);
            if (n < NN) {
                size_t base = (size_t)(b * NN + n) * C3 + headoff;
                kv = *(const float4*)&qkv[base + CC + c4 * 4];
                vv = *(const float4*)&qkv[base + 2 * CC + c4 * 4];
            }
            int d = c4 * 4;
            Kt[(d + 0) * 64 + r] = kv.x;
            Kt[(d + 1) * 64 + r] = kv.y;
            Kt[(d + 2) * 64 + r] = kv.z;
            Kt[(d + 3) * 64 + r] = kv.w;
            *(float4*)&Vs[r * 64 + d] = vv;
        }
        __syncthreads();

        float s[4][4];
        #pragma unroll
        for (int i = 0; i < 4; i++)
            #pragma unroll
            for (int j = 0; j < 4; j++) s[i][j] = 0.0f;
        #pragma unroll 8
        for (int d = 0; d < 64; d++) {
            float4 qa = *(const float4*)&Qt[d * 64 + ty * 4];
            float4 kb = *(const float4*)&Kt[d * 64 + tx * 4];
            float qq[4] = {qa.x, qa.y, qa.z, qa.w};
            float kk[4] = {kb.x, kb.y, kb.z, kb.w};
            #pragma unroll
            for (int i = 0; i < 4; i++)
                #pragma unroll
                for (int j = 0; j < 4; j++)
                    s[i][j] = fmaf(qq[i], kk[j], s[i][j]);
        }
        #pragma unroll
        for (int i = 0; i < 4; i++)
            #pragma unroll
            for (int j = 0; j < 4; j++) {
                int cix = kv0 + tx * 4 + j;
                Ss[(ty * 4 + i) * 64 + tx * 4 + j] =
                    (cix < NN) ? s[i][j] * scale : -INFINITY;
            }
        __syncthreads();

        {
            int r = tid >> 2;
            int part = tid & 3;
            float pv[16];
            #pragma unroll
            for (int j4 = 0; j4 < 4; j4++)
                *(float4*)&pv[j4 * 4] = *(const float4*)&Ss[r * 64 + part * 16 + j4 * 4];
            float lmax = pv[0];
            #pragma unroll
            for (int j = 1; j < 16; j++) lmax = fmaxf(lmax, pv[j]);
            lmax = fmaxf(lmax, __shfl_xor_sync(0xffffffffu, lmax, 1));
            lmax = fmaxf(lmax, __shfl_xor_sync(0xffffffffu, lmax, 2));
            float m_old = row_m[r];
            float m_new = fmaxf(m_old, lmax);
            float lsum = 0.0f;
            #pragma unroll
            for (int j = 0; j < 16; j++) {
                pv[j] = __expf(pv[j] - m_new);
                lsum += pv[j];
            }
            lsum += __shfl_xor_sync(0xffffffffu, lsum, 1);
            lsum += __shfl_xor_sync(0xffffffffu, lsum, 2);
            float sc = __expf(m_old - m_new);
            if (part == 0) {
                row_s[r] = sc;
                row_m[r] = m_new;
                row_l[r] = row_l[r] * sc + lsum;
            }
            __syncthreads();
            #pragma unroll
            for (int j = 0; j < 16; j++)
                Ss[(part * 16 + j) * 64 + r] = pv[j];
        }
        __syncthreads();

        float rs[4];
        #pragma unroll
        for (int i = 0; i < 4; i++) rs[i] = row_s[ty * 4 + i];
        #pragma unroll
        for (int i = 0; i < 4; i++)
            #pragma unroll
            for (int j = 0; j < 4; j++) acc[i][j] *= rs[i];
        #pragma unroll 8
        for (int kk2 = 0; kk2 < 64; kk2++) {
            float4 pa = *(const float4*)&Ss[kk2 * 64 + ty * 4];
            float4 vb = *(const float4*)&Vs[kk2 * 64 + tx * 4];
            float pp[4] = {pa.x, pa.y, pa.z, pa.w};
            float vv[4] = {vb.x, vb.y, vb.z, vb.w};
            #pragma unroll
            for (int i = 0; i < 4; i++)
                #pragma unroll
                for (int j = 0; j < 4; j++)
                    acc[i][j] = fmaf(pp[i], vv[j], acc[i][j]);
        }
    }

    #pragma unroll
    for (int i = 0; i < 4; i++) {
        int n = q0 + ty * 4 + i;
        if (n >= NN) continue;
        float inv = 1.0f / row_l[ty * 4 + i];
        float4 ov;
        ov.x = tf32r(acc[i][0] * inv);
        ov.y = tf32r(acc[i][1] * inv);
        ov.z = tf32r(acc[i][2] * inv);
        ov.w = tf32r(acc[i][3] * inv);
        *(float4*)&o[(size_t)(b * NN + n) * CC + headoff + tx * 4] = ov;
    }
}

// ---------------------------------------------------------------------------
// SwiGLU gate: hid = silu(x1) * x2, tf32-rounded (feeds w3 GEMM only)
// ---------------------------------------------------------------------------
__global__ void silu_kernel(float* __restrict__ x1, const float* __restrict__ x2)
{
    int idx = blockIdx.x * blockDim.x + threadIdx.x;
    int total4 = MM * HID / 4;
    if (idx >= total4) return;
    float4 a = ((const float4*)x1)[idx];
    float4 b = ((const float4*)x2)[idx];
    a.x = tf32r(a.x / (1.0f + __expf(-a.x)) * b.x);
    a.y = tf32r(a.y / (1.0f + __expf(-a.y)) * b.y);
    a.z = tf32r(a.z / (1.0f + __expf(-a.z)) * b.z);
    a.w = tf32r(a.w / (1.0f + __expf(-a.w)) * b.w);
    ((float4*)x1)[idx] = a;
}

// ---------------------------------------------------------------------------
// Launch
// ---------------------------------------------------------------------------
static inline void round_w(const float* in, float* out, int elems) {
    int n4 = elems / 4;
    round_tf32_kernel<<<(n4 + 255) / 256, 256>>>(in, out, n4);
}

extern "C" void kernel_launch(void* const* d_in, const int* in_sizes, int n_in,
                              void* d_out, int out_size)
{
    const float* x      = (const float*)d_in[0];
    const float* freqs  = (const float*)d_in[1];
    const float* ln1_g  = (const float*)d_in[2];
    const float* ln1_b  = (const float*)d_in[3];
    const float* qkv_w  = (const float*)d_in[4];
    const float* qkv_b  = (const float*)d_in[5];
    const float* proj_w = (const float*)d_in[6];
    const float* proj_b = (const float*)d_in[7];
    const float* ln2_g  = (const float*)d_in[8];
    const float* ln2_b  = (const float*)d_in[9];
    const float* w1     = (const float*)d_in[10];
    const float* b1     = (const float*)d_in[11];
    const float* w2     = (const float*)d_in[12];
    const float* b2     = (const float*)d_in[13];
    const float* w3     = (const float*)d_in[14];
    const float* b3     = (const float*)d_in[15];
    float* out = (float*)d_out;

    float *h_buf, *qkv_buf, *attn_buf, *x1_buf, *x2_buf, *wr;
    cudaGetSymbolAddress((void**)&h_buf, g_h);
    cudaGetSymbolAddress((void**)&qkv_buf, g_qkv);
    cudaGetSymbolAddress((void**)&attn_buf, g_attn);
    cudaGetSymbolAddress((void**)&x1_buf, g_x1);
    cudaGetSymbolAddress((void**)&x2_buf, g_x2);
    cudaGetSymbolAddress((void**)&wr, g_wr);

    cudaFuncSetAttribute(gemm_tf32<false>,
                         cudaFuncAttributeMaxDynamicSharedMemorySize, GM_SMEM);
    cudaFuncSetAttribute(gemm_tf32<true>,
                         cudaFuncAttributeMaxDynamicSharedMemorySize, GM_SMEM);

    const int mblocks = (MM + 127) / 128;   // 86

    // 0) round weights to tf32
    round_w(qkv_w,  wr + WR_QKV,  C3 * CC);
    round_w(proj_w, wr + WR_PROJ, CC * CC);
    round_w(w1,     wr + WR_W1,   HID * CC);
    round_w(w2,     wr + WR_W2,   HID * CC);
    round_w(w3,     wr + WR_W3,   CC * HID);

    // 1) LN1 (tf32-rounded output)
    ln_kernel<<<MM, 256>>>(x, ln1_g, ln1_b, h_buf);

    // 2) QKV GEMM: [M,768] x [2304,768]^T
    gemm_tf32<false><<<dim3(C3 / 128, mblocks), 256, GM_SMEM>>>(
        h_buf, wr + WR_QKV, qkv_b, nullptr, qkv_buf, MM, C3, CC);

    // 3) RoPE in place
    {
        int total = MM * 768;
        rope_kernel<<<(total + 255) / 256, 256>>>(qkv_buf, freqs);
    }

    // 4) Flash attention (output tf32-rounded)
    {
        int smem = (4 * 64 * 64 + 3 * 64) * (int)sizeof(float);
        cudaFuncSetAttribute(flash_attn_kernel,
                             cudaFuncAttributeMaxDynamicSharedMemorySize, smem);
        dim3 grid((NN + 63) / 64, BB * HH);
        flash_attn_kernel<<<grid, 256, smem>>>(qkv_buf, attn_buf);
    }

    // 5) proj GEMM + residual(x) -> out
    gemm_tf32<true><<<dim3(CC / 128, mblocks), 256, GM_SMEM>>>(
        attn_buf, wr + WR_PROJ, proj_b, x, out, MM, CC, CC);

    // 6) LN2
    ln_kernel<<<MM, 256>>>(out, ln2_g, ln2_b, h_buf);

    // 7/8) x1, x2 GEMMs
    gemm_tf32<false><<<dim3(HID / 128, mblocks), 256, GM_SMEM>>>(
        h_buf, wr + WR_W1, b1, nullptr, x1_buf, MM, HID, CC);
    gemm_tf32<false><<<dim3(HID / 128, mblocks), 256, GM_SMEM>>>(
        h_buf, wr + WR_W2, b2, nullptr, x2_buf, MM, HID, CC);

    // 9) hid = silu(x1) * x2 (tf32-rounded)
    {
        int total4 = MM * HID / 4;
        silu_kernel<<<(total4 + 255) / 256, 256>>>(x1_buf, x2_buf);
    }

    // 10) mlp GEMM + residual -> out
    gemm_tf32<true><<<dim3(CC / 128, mblocks), 256, GM_SMEM>>>(
        x1_buf, wr + WR_W3, b3, out, out, MM, CC, HID);
}

// round 11
// speedup vs baseline: 2.7120x; 1.3938x over previous
#include <cuda_runtime.h>
#include <cuda_bf16.h>
#include <math.h>
#include <stdint.h>

// ---------------------------------------------------------------------------
// Problem constants
// ---------------------------------------------------------------------------
#define BB   8
#define NN   1374
#define CC   768
#define HH   12
#define HD   64
#define C3   2304
#define HID  3072
#define MM   (BB * NN)          // 10992 rows
#define LN_EPS 1e-5f

// ---------------------------------------------------------------------------
// Scratch (device globals; no allocations allowed)
// ---------------------------------------------------------------------------
__device__ float g_h[MM * CC];          // LN output (tf32-rounded)
__device__ float g_qkv[MM * C3];        // QKV output (RoPE in place, fp32)
__device__ float g_attn[MM * CC];       // attention output (tf32-rounded)
__device__ float g_x1[MM * HID];        // MLP x1 -> hid (tf32-rounded after silu)
__device__ float g_x2[MM * HID];        // MLP x2
// tf32-rounded weight copies
#define WR_QKV  0
#define WR_PROJ 1769472
#define WR_W1   2359296
#define WR_W2   4718592
#define WR_W3   7077888
#define WR_TOT  9437184
__device__ float g_wr[WR_TOT];

// ---------------------------------------------------------------------------
// Helpers
// ---------------------------------------------------------------------------
__device__ __forceinline__ float tf32r(float x) {
    uint32_t o, i = __float_as_uint(x);
    asm("cvt.rna.tf32.f32 %0, %1;" : "=r"(o) : "r"(i));
    return __uint_as_float(o);
}
__device__ __forceinline__ uint32_t smem_u32(const void* p) {
    uint32_t a;
    asm("{ .reg .u64 t; cvta.to.shared.u64 t, %1; cvt.u32.u64 %0, t; }"
        : "=r"(a) : "l"(p));
    return a;
}
__device__ __forceinline__ void cp_async16(uint32_t dst, const void* src, uint32_t sz) {
    asm volatile("cp.async.cg.shared.global [%0], [%1], 16, %2;"
                 :: "r"(dst), "l"(src), "r"(sz));
}
#define CP_COMMIT() asm volatile("cp.async.commit_group;" ::: "memory")
#define CP_WAIT1()  asm volatile("cp.async.wait_group 1;" ::: "memory")

__device__ __forceinline__ void mma_tf32(float* d, const uint32_t* a, const uint32_t* b) {
    asm volatile(
        "mma.sync.aligned.m16n8k8.row.col.f32.tf32.tf32.f32 "
        "{%0,%1,%2,%3}, {%4,%5,%6,%7}, {%8,%9}, {%0,%1,%2,%3};"
        : "+f"(d[0]), "+f"(d[1]), "+f"(d[2]), "+f"(d[3])
        : "r"(a[0]), "r"(a[1]), "r"(a[2]), "r"(a[3]), "r"(b[0]), "r"(b[1]));
}

// ---------------------------------------------------------------------------
// Round fp32 -> tf32 bit pattern (weights)
// ---------------------------------------------------------------------------
__global__ void round_tf32_kernel(const float* __restrict__ in,
                                  float* __restrict__ out, int n4)
{
    int idx = blockIdx.x * blockDim.x + threadIdx.x;
    if (idx >= n4) return;
    float4 v = ((const float4*)in)[idx];
    v.x = tf32r(v.x); v.y = tf32r(v.y); v.z = tf32r(v.z); v.w = tf32r(v.w);
    ((float4*)out)[idx] = v;
}

// ---------------------------------------------------------------------------
// tf32 tensor-core NT GEMM (unchanged from R9 — passing, ~170 TF/s)
// ---------------------------------------------------------------------------
#define GM_LDS  20
#define GM_ASTF (128 * GM_LDS)
#define GM_STF  (2 * GM_ASTF)
#define GM_SMEM (3 * GM_STF * 4)

template <bool RES>
__global__ void __launch_bounds__(256, 2)
gemm_tf32(const float* __restrict__ A, const float* __restrict__ W,
          const float* __restrict__ bias, const float* R, float* __restrict__ out,
          int M, int N, int K)
{
    extern __shared__ float sm[];
    const uint32_t sb = smem_u32(sm);
    const int tid  = threadIdx.x;
    const int warp = tid >> 5;
    const int lane = tid & 31;
    const int wm = warp >> 2;
    const int wn = warp & 3;
    const int r = lane >> 2;
    const int c = lane & 3;
    const int m0 = blockIdx.y * 128;
    const int n0 = blockIdx.x * 128;

    const int row_l = tid >> 2;
    const int c4    = tid & 3;

    float acc[4][4][4];
    #pragma unroll
    for (int i = 0; i < 4; i++)
        #pragma unroll
        for (int j = 0; j < 4; j++)
            #pragma unroll
            for (int e = 0; e < 4; e++) acc[i][j][e] = 0.0f;

    const int nchunk = K >> 4;

    auto load_stage = [&](int s, int ch) {
        const int k0 = ch << 4;
        const uint32_t sa = sb + (uint32_t)(s * GM_STF) * 4u;
        #pragma unroll
        for (int p = 0; p < 2; p++) {
            int row = row_l + p * 64;
            int gm = m0 + row;
            int gms = gm < M ? gm : M - 1;
            const float* src = A + (size_t)gms * K + k0 + c4 * 4;
            uint32_t dst = sa + (uint32_t)(row * GM_LDS + c4 * 4) * 4u;
            cp_async16(dst, src, gm < M ? 16u : 0u);
        }
        #pragma unroll
        for (int p = 0; p < 2; p++) {
            int row = row_l + p * 64;
            const float* src = W + (size_t)(n0 + row) * K + k0 + c4 * 4;
            uint32_t dst = sa + (uint32_t)(GM_ASTF + row * GM_LDS + c4 * 4) * 4u;
            cp_async16(dst, src, 16u);
        }
    };

    load_stage(0, 0); CP_COMMIT();
    load_stage(1, 1); CP_COMMIT();

    for (int ch = 0; ch < nchunk; ch++) {
        int s = ch % 3;
        CP_WAIT1();
        __syncthreads();
        if (ch + 2 < nchunk) load_stage((ch + 2) % 3, ch + 2);
        CP_COMMIT();

        const float* As = sm + s * GM_STF;
        const float* Bs = As + GM_ASTF;
        const float* ab = As + (wm * 64 + r) * GM_LDS + c;
        const float* bb = Bs + (wn * 32 + r) * GM_LDS + c;

        #pragma unroll
        for (int ks = 0; ks < 2; ks++) {
            uint32_t af[4][4], bf[4][2];
            #pragma unroll
            for (int i = 0; i < 4; i++) {
                const float* pa = ab + i * 16 * GM_LDS + ks * 8;
                af[i][0] = __float_as_uint(pa[0]);
                af[i][1] = __float_as_uint(pa[8 * GM_LDS]);
                af[i][2] = __float_as_uint(pa[4]);
                af[i][3] = __float_as_uint(pa[8 * GM_LDS + 4]);
            }
            #pragma unroll
            for (int j = 0; j < 4; j++) {
                const float* pb = bb + j * 8 * GM_LDS + ks * 8;
                bf[j][0] = __float_as_uint(pb[0]);
                bf[j][1] = __float_as_uint(pb[4]);
            }
            #pragma unroll
            for (int i = 0; i < 4; i++)
                #pragma unroll
                for (int j = 0; j < 4; j++)
                    mma_tf32(acc[i][j], af[i], bf[j]);
        }
    }

    #pragma unroll
    for (int i = 0; i < 4; i++) {
        int gr0 = m0 + wm * 64 + i * 16 + r;
        int gr1 = gr0 + 8;
        #pragma unroll
        for (int j = 0; j < 4; j++) {
            int gn = n0 + wn * 32 + j * 8 + 2 * c;
            float2 b2 = *(const float2*)&bias[gn];
            if (gr0 < M) {
                float2 o;
                o.x = acc[i][j][0] + b2.x;
                o.y = acc[i][j][1] + b2.y;
                if (RES) {
                    float2 r2 = *(const float2*)&R[(size_t)gr0 * N + gn];
                    o.x += r2.x; o.y += r2.y;
                }
                *(float2*)&out[(size_t)gr0 * N + gn] = o;
            }
            if (gr1 < M) {
                float2 o;
                o.x = acc[i][j][2] + b2.x;
                o.y = acc[i][j][3] + b2.y;
                if (RES) {
                    float2 r2 = *(const float2*)&R[(size_t)gr1 * N + gn];
                    o.x += r2.x; o.y += r2.y;
                }
                *(float2*)&out[(size_t)gr1 * N + gn] = o;
            }
        }
    }
}

// ---------------------------------------------------------------------------
// LayerNorm (tf32-rounded output; unchanged)
// ---------------------------------------------------------------------------
__global__ void ln_kernel(const float* __restrict__ x,
                          const float* __restrict__ g,
                          const float* __restrict__ b,
                          float* __restrict__ out)
{
    int row = blockIdx.x;
    int tid = threadIdx.x;
    int lane = tid & 31;
    int wid  = tid >> 5;
    const float* xr = x + (size_t)row * CC;

    float v0 = xr[tid];
    float v1 = xr[tid + 256];
    float v2 = xr[tid + 512];

    __shared__ float red[8];

    float s = v0 + v1 + v2;
    #pragma unroll
    for (int off = 16; off > 0; off >>= 1) s += __shfl_xor_sync(0xffffffffu, s, off);
    if (lane == 0) red[wid] = s;
    __syncthreads();
    float tot = red[0] + red[1] + red[2] + red[3] + red[4] + red[5] + red[6] + red[7];
    float mean = tot * (1.0f / (float)CC);
    __syncthreads();

    float d0 = v0 - mean, d1 = v1 - mean, d2 = v2 - mean;
    float sq = d0 * d0 + d1 * d1 + d2 * d2;
    #pragma unroll
    for (int off = 16; off > 0; off >>= 1) sq += __shfl_xor_sync(0xffffffffu, sq, off);
    if (lane == 0) red[wid] = sq;
    __syncthreads();
    float tot2 = red[0] + red[1] + red[2] + red[3] + red[4] + red[5] + red[6] + red[7];
    float var = tot2 * (1.0f / (float)CC);
    float rstd = rsqrtf(var + LN_EPS);

    float* orow = out + (size_t)row * CC;
    orow[tid]       = tf32r(d0 * rstd * g[tid]       + b[tid]);
    orow[tid + 256] = tf32r(d1 * rstd * g[tid + 256] + b[tid + 256]);
    orow[tid + 512] = tf32r(d2 * rstd * g[tid + 512] + b[tid + 512]);
}

// ---------------------------------------------------------------------------
// RoPE in place (unchanged)
// ---------------------------------------------------------------------------
__global__ void rope_kernel(float* __restrict__ qkv,
                            const float* __restrict__ freqs)
{
    int idx = blockIdx.x * blockDim.x + threadIdx.x;
    if (idx >= MM * 768) return;
    int m   = idx / 768;
    int rem = idx % 768;
    int s   = rem / 384;
    int hr  = rem % 384;
    int h   = hr >> 5;
    int dd  = hr & 31;
    int n   = m % NN;

    size_t base = (size_t)m * C3 + s * CC + h * HD;
    float f1 = freqs[n * HD + dd];
    float f2 = freqs[n * HD + dd + 32];
    float c1, s1, c2, s2;
    sincosf(f1, &s1, &c1);
    sincosf(f2, &s2, &c2);
    float x1 = qkv[base + dd];
    float x2 = qkv[base + dd + 32];
    qkv[base + dd]      = x1 * c1 - x2 * s1;
    qkv[base + dd + 32] = x2 * c2 + x1 * s2;
}

// ---------------------------------------------------------------------------
// tf32 tensor-core flash attention. BQ=BKV=64, 8 warps (4m x 2n), warp tile
// 16x32. S=Q@K^T and O+=P@V via mma.sync m16n8k8. Softmax in fp32.
// Smem tiles [64][68] fp32 (pad-68: conflict-free fragment LDS).
// Scale folded into Q; key-mask applied in softmax stage (last tile only).
// ---------------------------------------------------------------------------
#define FA_LD 68
#define FA_TILE (64 * FA_LD)
#define FA_SMEM ((4 * FA_TILE + 3 * 64) * 4)   // 70400 bytes

__global__ void __launch_bounds__(256)
flash_tf32_kernel(const float* __restrict__ qkv, float* __restrict__ o)
{
    extern __shared__ float sm[];
    float* Qs    = sm;                   // [q][d]   ld 68 (pre-scaled, tf32)
    float* Ks    = Qs + FA_TILE;         // [kv][d]  ld 68 (tf32)
    float* Vt    = Ks + FA_TILE;         // [d][kv]  ld 68 (tf32)
    float* Ss    = Vt + FA_TILE;         // [q][kv]  ld 68 (S then P in place)
    float* row_m = Ss + FA_TILE;
    float* row_l = row_m + 64;
    float* row_s = row_l + 64;

    const int tid  = threadIdx.x;
    const int warp = tid >> 5;
    const int lane = tid & 31;
    const int wm = warp & 3;             // m strip *16
    const int wn = warp >> 2;            // n strip *32
    const int fr = lane >> 2;            // 0..7
    const int fc = lane & 3;             // 0..3
    const int q0 = blockIdx.x * 64;
    const int b  = blockIdx.y / HH;
    const int h  = blockIdx.y % HH;
    const size_t headoff = (size_t)h * HD;

    if (tid < 64) { row_m[tid] = -INFINITY; row_l[tid] = 0.0f; }

    // Q tile load: scale by 0.125, tf32 round
    #pragma unroll
    for (int i = 0; i < 4; i++) {
        int idx = tid + i * 256;
        int r = idx >> 4, c4 = idx & 15;
        int n = q0 + r;
        float4 v = make_float4(0.f, 0.f, 0.f, 0.f);
        if (n < NN) v = *(const float4*)&qkv[(size_t)(b * NN + n) * C3 + headoff + c4 * 4];
        float4 w;
        w.x = tf32r(v.x * 0.125f); w.y = tf32r(v.y * 0.125f);
        w.z = tf32r(v.z * 0.125f); w.w = tf32r(v.w * 0.125f);
        *(float4*)&Qs[r * FA_LD + c4 * 4] = w;
    }

    float oacc[4][4];
    #pragma unroll
    for (int j = 0; j < 4; j++)
        #pragma unroll
        for (int e = 0; e < 4; e++) oacc[j][e] = 0.0f;

    const int ntiles = (NN + 63) / 64;   // 22

    for (int t = 0; t < ntiles; t++) {
        const int kv0 = t * 64;
        __syncthreads();                 // prior Ks/Vt/Ss readers done

        // K tile [kv][d] + V tile transposed [d][kv]
        #pragma unroll
        for (int i = 0; i < 4; i++) {
            int idx = tid + i * 256;
            int r = idx >> 4, c4 = idx & 15;
            int n = kv0 + r;
            float4 kv = make_float4(0.f, 0.f, 0.f, 0.f);
            float4 vv = make_float4(0.f, 0.f, 0.f, 0.f);
            if (n < NN) {
                size_t base = (size_t)(b * NN + n) * C3 + headoff;
                kv = *(const float4*)&qkv[base + CC + c4 * 4];
                vv = *(const float4*)&qkv[base + 2 * CC + c4 * 4];
            }
            float4 kw;
            kw.x = tf32r(kv.x); kw.y = tf32r(kv.y);
            kw.z = tf32r(kv.z); kw.w = tf32r(kv.w);
            *(float4*)&Ks[r * FA_LD + c4 * 4] = kw;
            int d = c4 * 4;
            Vt[(d + 0) * FA_LD + r] = tf32r(vv.x);
            Vt[(d + 1) * FA_LD + r] = tf32r(vv.y);
            Vt[(d + 2) * FA_LD + r] = tf32r(vv.z);
            Vt[(d + 3) * FA_LD + r] = tf32r(vv.w);
        }
        __syncthreads();

        // S = Q @ K^T (warp tile 16x32, 8 k-steps)
        float sacc[4][4];
        #pragma unroll
        for (int j = 0; j < 4; j++)
            #pragma unroll
            for (int e = 0; e < 4; e++) sacc[j][e] = 0.0f;
        {
            const float* ab = Qs + (wm * 16 + fr) * FA_LD + fc;
            const float* bb = Ks + (wn * 32 + fr) * FA_LD + fc;
            #pragma unroll
            for (int ks = 0; ks < 8; ks++) {
                uint32_t af[4], bf[2];
                const float* pa = ab + ks * 8;
                af[0] = __float_as_uint(pa[0]);
                af[1] = __float_as_uint(pa[8 * FA_LD]);
                af[2] = __float_as_uint(pa[4]);
                af[3] = __float_as_uint(pa[8 * FA_LD + 4]);
                #pragma unroll
                for (int j = 0; j < 4; j++) {
                    const float* pb = bb + j * 8 * FA_LD + ks * 8;
                    bf[0] = __float_as_uint(pb[0]);
                    bf[1] = __float_as_uint(pb[4]);
                    mma_tf32(sacc[j], af, bf);
                }
            }
        }
        // write S fragments (row-major, no scale — folded into Q)
        #pragma unroll
        for (int j = 0; j < 4; j++) {
            float* d0 = Ss + (wm * 16 + fr) * FA_LD + wn * 32 + j * 8 + 2 * fc;
            d0[0] = sacc[j][0]; d0[1] = sacc[j][1];
            float* d1 = d0 + 8 * FA_LD;
            d1[0] = sacc[j][2]; d1[1] = sacc[j][3];
        }
        __syncthreads();

        // online softmax: 4 lanes per row, 16 cols each (in place)
        {
            int r = tid >> 2;
            int part = tid & 3;
            float pv[16];
            #pragma unroll
            for (int j4 = 0; j4 < 4; j4++)
                *(float4*)&pv[j4 * 4] = *(const float4*)&Ss[r * FA_LD + part * 16 + j4 * 4];
            if (kv0 + 64 > NN) {         // key mask, last tile only
                #pragma unroll
                for (int j = 0; j < 16; j++)
                    if (kv0 + part * 16 + j >= NN) pv[j] = -INFINITY;
            }
            float lmax = pv[0];
            #pragma unroll
            for (int j = 1; j < 16; j++) lmax = fmaxf(lmax, pv[j]);
            lmax = fmaxf(lmax, __shfl_xor_sync(0xffffffffu, lmax, 1));
            lmax = fmaxf(lmax, __shfl_xor_sync(0xffffffffu, lmax, 2));
            float m_old = row_m[r];
            float m_new = fmaxf(m_old, lmax);
            float lsum = 0.0f;
            #pragma unroll
            for (int j = 0; j < 16; j++) {
                pv[j] = __expf(pv[j] - m_new);    // exp(-inf)=0 handles mask
                lsum += pv[j];
            }
            lsum += __shfl_xor_sync(0xffffffffu, lsum, 1);
            lsum += __shfl_xor_sync(0xffffffffu, lsum, 2);
            float sc = __expf(m_old - m_new);     // m_old=-inf -> 0
            if (part == 0) {
                row_s[r] = sc;
                row_m[r] = m_new;
                row_l[r] = row_l[r] * sc + lsum;
            }
            // write P back in place (tf32-rounded for the mma)
            #pragma unroll
            for (int j4 = 0; j4 < 4; j4++) {
                float4 w;
                w.x = tf32r(pv[j4 * 4 + 0]);
                w.y = tf32r(pv[j4 * 4 + 1]);
                w.z = tf32r(pv[j4 * 4 + 2]);
                w.w = tf32r(pv[j4 * 4 + 3]);
                *(float4*)&Ss[r * FA_LD + part * 16 + j4 * 4] = w;
            }
        }
        __syncthreads();                 // P + row_s visible

        // rescale O and accumulate P @ V
        {
            float rs0 = row_s[wm * 16 + fr];
            float rs1 = row_s[wm * 16 + fr + 8];
            #pragma unroll
            for (int j = 0; j < 4; j++) {
                oacc[j][0] *= rs0; oacc[j][1] *= rs0;
                oacc[j][2] *= rs1; oacc[j][3] *= rs1;
            }
            const float* ap = Ss + (wm * 16 + fr) * FA_LD + fc;
            const float* bp = Vt + (wn * 32 + fr) * FA_LD + fc;
            #pragma unroll
            for (int ks = 0; ks < 8; ks++) {
                uint32_t af[4], bf[2];
                const float* pa = ap + ks * 8;
                af[0] = __float_as_uint(pa[0]);
                af[1] = __float_as_uint(pa[8 * FA_LD]);
                af[2] = __float_as_uint(pa[4]);
                af[3] = __float_as_uint(pa[8 * FA_LD + 4]);
                #pragma unroll
                for (int j = 0; j < 4; j++) {
                    const float* pb = bp + j * 8 * FA_LD + ks * 8;
                    bf[0] = __float_as_uint(pb[0]);
                    bf[1] = __float_as_uint(pb[4]);
                    mma_tf32(oacc[j], af, bf);
                }
            }
        }
    }

    // normalize + store (tf32-rounded; feeds proj GEMM)
    {
        int r0 = wm * 16 + fr;
        float inv0 = 1.0f / row_l[r0];
        float inv1 = 1.0f / row_l[r0 + 8];
        int n0g = q0 + r0;
        int n1g = n0g + 8;
        #pragma unroll
        for (int j = 0; j < 4; j++) {
            size_t col = headoff + wn * 32 + j * 8 + 2 * fc;
            if (n0g < NN) {
                float2 ov;
                ov.x = tf32r(oacc[j][0] * inv0);
                ov.y = tf32r(oacc[j][1] * inv0);
                *(float2*)&o[(size_t)(b * NN + n0g) * CC + col] = ov;
            }
            if (n1g < NN) {
                float2 ov;
                ov.x = tf32r(oacc[j][2] * inv1);
                ov.y = tf32r(oacc[j][3] * inv1);
                *(float2*)&o[(size_t)(b * NN + n1g) * CC + col] = ov;
            }
        }
    }
}

// ---------------------------------------------------------------------------
// SwiGLU gate (tf32-rounded; unchanged)
// ---------------------------------------------------------------------------
__global__ void silu_kernel(float* __restrict__ x1, const float* __restrict__ x2)
{
    int idx = blockIdx.x * blockDim.x + threadIdx.x;
    int total4 = MM * HID / 4;
    if (idx >= total4) return;
    float4 a = ((const float4*)x1)[idx];
    float4 b = ((const float4*)x2)[idx];
    a.x = tf32r(a.x / (1.0f + __expf(-a.x)) * b.x);
    a.y = tf32r(a.y / (1.0f + __expf(-a.y)) * b.y);
    a.z = tf32r(a.z / (1.0f + __expf(-a.z)) * b.z);
    a.w = tf32r(a.w / (1.0f + __expf(-a.w)) * b.w);
    ((float4*)x1)[idx] = a;
}

// ---------------------------------------------------------------------------
// Launch
// ---------------------------------------------------------------------------
static inline void round_w(const float* in, float* out, int elems) {
    int n4 = elems / 4;
    round_tf32_kernel<<<(n4 + 255) / 256, 256>>>(in, out, n4);
}

extern "C" void kernel_launch(void* const* d_in, const int* in_sizes, int n_in,
                              void* d_out, int out_size)
{
    const float* x      = (const float*)d_in[0];
    const float* freqs  = (const float*)d_in[1];
    const float* ln1_g  = (const float*)d_in[2];
    const float* ln1_b  = (const float*)d_in[3];
    const float* qkv_w  = (const float*)d_in[4];
    const float* qkv_b  = (const float*)d_in[5];
    const float* proj_w = (const float*)d_in[6];
    const float* proj_b = (const float*)d_in[7];
    const float* ln2_g  = (const float*)d_in[8];
    const float* ln2_b  = (const float*)d_in[9];
    const float* w1     = (const float*)d_in[10];
    const float* b1     = (const float*)d_in[11];
    const float* w2     = (const float*)d_in[12];
    const float* b2     = (const float*)d_in[13];
    const float* w3     = (const float*)d_in[14];
    const float* b3     = (const float*)d_in[15];
    float* out = (float*)d_out;

    float *h_buf, *qkv_buf, *attn_buf, *x1_buf, *x2_buf, *wr;
    cudaGetSymbolAddress((void**)&h_buf, g_h);
    cudaGetSymbolAddress((void**)&qkv_buf, g_qkv);
    cudaGetSymbolAddress((void**)&attn_buf, g_attn);
    cudaGetSymbolAddress((void**)&x1_buf, g_x1);
    cudaGetSymbolAddress((void**)&x2_buf, g_x2);
    cudaGetSymbolAddress((void**)&wr, g_wr);

    cudaFuncSetAttribute(gemm_tf32<false>,
                         cudaFuncAttributeMaxDynamicSharedMemorySize, GM_SMEM);
    cudaFuncSetAttribute(gemm_tf32<true>,
                         cudaFuncAttributeMaxDynamicSharedMemorySize, GM_SMEM);
    cudaFuncSetAttribute(flash_tf32_kernel,
                         cudaFuncAttributeMaxDynamicSharedMemorySize, FA_SMEM);

    const int mblocks = (MM + 127) / 128;   // 86

    // 0) round weights to tf32
    round_w(qkv_w,  wr + WR_QKV,  C3 * CC);
    round_w(proj_w, wr + WR_PROJ, CC * CC);
    round_w(w1,     wr + WR_W1,   HID * CC);
    round_w(w2,     wr + WR_W2,   HID * CC);
    round_w(w3,     wr + WR_W3,   CC * HID);

    // 1) LN1 (tf32-rounded output)
    ln_kernel<<<MM, 256>>>(x, ln1_g, ln1_b, h_buf);

    // 2) QKV GEMM: [M,768] x [2304,768]^T
    gemm_tf32<false><<<dim3(C3 / 128, mblocks), 256, GM_SMEM>>>(
        h_buf, wr + WR_QKV, qkv_b, nullptr, qkv_buf, MM, C3, CC);

    // 3) RoPE in place
    {
        int total = MM * 768;
        rope_kernel<<<(total + 255) / 256, 256>>>(qkv_buf, freqs);
    }

    // 4) Flash attention (tf32 tensor cores)
    {
        dim3 grid((NN + 63) / 64, BB * HH);   // (22, 96)
        flash_tf32_kernel<<<grid, 256, FA_SMEM>>>(qkv_buf, attn_buf);
    }

    // 5) proj GEMM + residual(x) -> out
    gemm_tf32<true><<<dim3(CC / 128, mblocks), 256, GM_SMEM>>>(
        attn_buf, wr + WR_PROJ, proj_b, x, out, MM, CC, CC);

    // 6) LN2
    ln_kernel<<<MM, 256>>>(out, ln2_g, ln2_b, h_buf);

    // 7/8) x1, x2 GEMMs
    gemm_tf32<false><<<dim3(HID / 128, mblocks), 256, GM_SMEM>>>(
        h_buf, wr + WR_W1, b1, nullptr, x1_buf, MM, HID, CC);
    gemm_tf32<false><<<dim3(HID / 128, mblocks), 256, GM_SMEM>>>(
        h_buf, wr + WR_W2, b2, nullptr, x2_buf, MM, HID, CC);

    // 9) hid = silu(x1) * x2 (tf32-rounded)
    {
        int total4 = MM * HID / 4;
        silu_kernel<<<(total4 + 255) / 256, 256>>>(x1_buf, x2_buf);
    }

    // 10) mlp GEMM + residual -> out
    gemm_tf32<true><<<dim3(CC / 128, mblocks), 256, GM_SMEM>>>(
        x1_buf, wr + WR_W3, b3, out, out, MM, CC, HID);
}

// round 13
// speedup vs baseline: 4.3589x; 1.6073x over previous
#include <cuda_runtime.h>
#include <cuda_fp16.h>
#include <math.h>
#include <stdint.h>

// ---------------------------------------------------------------------------
// Problem constants
// ---------------------------------------------------------------------------
#define BB   8
#define NN   1374
#define CC   768
#define HH   12
#define HD   64
#define C3   2304
#define HID  3072
#define MM   (BB * NN)          // 10992 rows
#define LN_EPS 1e-5f

// ---------------------------------------------------------------------------
// Scratch (device globals; no allocations allowed)
// ---------------------------------------------------------------------------
__device__ __half g_h[MM * CC];         // LN output (fp16)
__device__ float  g_qkv[MM * C3];       // QKV output (RoPE in place, fp32)
__device__ __half g_attn[MM * CC];      // attention output (fp16)
__device__ float  g_x1[MM * HID];       // MLP x1 (fp32, read by fused silu)
__device__ __half g_hid[MM * HID];      // silu(x1)*x2 (fp16)
// fp16 weight copies (element offsets)
#define WH_QKV  0
#define WH_PROJ 1769472
#define WH_W1   2359296
#define WH_W2   4718592
#define WH_W3   7077888
#define WH_TOT  9437184
__device__ __half g_wh[WH_TOT];

// ---------------------------------------------------------------------------
// Helpers
// ---------------------------------------------------------------------------
__device__ __forceinline__ uint32_t smem_u32(const void* p) {
    uint32_t a;
    asm("{ .reg .u64 t; cvta.to.shared.u64 t, %1; cvt.u32.u64 %0, t; }"
        : "=r"(a) : "l"(p));
    return a;
}
__device__ __forceinline__ void cp_async16(uint32_t dst, const void* src, uint32_t sz) {
    asm volatile("cp.async.cg.shared.global [%0], [%1], 16, %2;"
                 :: "r"(dst), "l"(src), "r"(sz));
}
#define CP_COMMIT() asm volatile("cp.async.commit_group;" ::: "memory")
#define CP_WAIT1()  asm volatile("cp.async.wait_group 1;" ::: "memory")

__device__ __forceinline__ uint32_t ldh2(const __half* p) {
    return *(const uint32_t*)p;          // aligned half2 load
}
__device__ __forceinline__ void mma_f16(float* d, const uint32_t* a, const uint32_t* b) {
    asm volatile(
        "mma.sync.aligned.m16n8k16.row.col.f32.f16.f16.f32 "
        "{%0,%1,%2,%3}, {%4,%5,%6,%7}, {%8,%9}, {%0,%1,%2,%3};"
        : "+f"(d[0]), "+f"(d[1]), "+f"(d[2]), "+f"(d[3])
        : "r"(a[0]), "r"(a[1]), "r"(a[2]), "r"(a[3]), "r"(b[0]), "r"(b[1]));
}

// ---------------------------------------------------------------------------
// fp32 -> fp16 conversion (weights)
// ---------------------------------------------------------------------------
__global__ void f2h_kernel(const float* __restrict__ in,
                           __half* __restrict__ out, int n4)
{
    int idx = blockIdx.x * blockDim.x + threadIdx.x;
    if (idx >= n4) return;
    float4 v = ((const float4*)in)[idx];
    __half2 h0 = __floats2half2_rn(v.x, v.y);
    __half2 h1 = __floats2half2_rn(v.z, v.w);
    ((__half2*)out)[idx * 2]     = h0;
    ((__half2*)out)[idx * 2 + 1] = h1;
}

// ---------------------------------------------------------------------------
// fp16 tensor-core NT GEMM: out[m,n] = sum_k A[m,k]*W[n,k] + bias[n] ...
// MODE 0: out fp32.  MODE 1: out fp32 + residual R.  MODE 2: fused SwiGLU —
//   reads G (=x1, fp32), writes half out = silu(G) * (acc + bias).
// BM=BN=128, BK=32 halves, 8 warps (2m x 4n), warp tile 64x32, 3-stage cp.async.
// Smem rows padded to 40 halves (80 B) — conflict-free fragment half2 loads.
// ---------------------------------------------------------------------------
#define HG_LD   40
#define HG_ASTF (128 * HG_LD)            // 5120 halves per A stage
#define HG_STF  (2 * HG_ASTF)            // 10240 halves per stage
#define HG_SMEM (3 * HG_STF * 2)         // 61440 bytes

template <int MODE>
__global__ void __launch_bounds__(256, 2)
gemm_f16(const __half* __restrict__ A, const __half* __restrict__ W,
         const float* __restrict__ bias, const float* __restrict__ RG,
         void* __restrict__ outp, int M, int N, int K)
{
    extern __shared__ __half smh[];
    const uint32_t sb = smem_u32(smh);
    const int tid  = threadIdx.x;
    const int warp = tid >> 5;
    const int lane = tid & 31;
    const int wm = warp >> 2;            // 0..1 (m strip *64)
    const int wn = warp & 3;             // 0..3 (n strip *32)
    const int r = lane >> 2;             // 0..7
    const int c = lane & 3;              // 0..3
    const int m0 = blockIdx.y * 128;
    const int n0 = blockIdx.x * 128;

    float acc[4][4][4];
    #pragma unroll
    for (int i = 0; i < 4; i++)
        #pragma unroll
        for (int j = 0; j < 4; j++)
            #pragma unroll
            for (int e = 0; e < 4; e++) acc[i][j][e] = 0.0f;

    const int nchunk = K >> 5;           // BK=32

    auto load_stage = [&](int s, int ch) {
        const int k0 = ch << 5;
        const uint32_t sa = sb + (uint32_t)(s * HG_STF) * 2u;
        // A tile: 128 rows x 32 halves (4 x 16B per row); 512 chunks / 256 thr
        #pragma unroll
        for (int i = 0; i < 2; i++) {
            int idx = tid + i * 256;
            int row = idx >> 2, ch16 = idx & 3;
            int gm = m0 + row;
            int gms = gm < M ? gm : M - 1;
            const __half* src = A + (size_t)gms * K + k0 + ch16 * 8;
            uint32_t dst = sa + (uint32_t)(row * HG_LD + ch16 * 8) * 2u;
            cp_async16(dst, src, gm < M ? 16u : 0u);
        }
        // B tile: 128 rows x 32 halves (N always multiple of 128)
        #pragma unroll
        for (int i = 0; i < 2; i++) {
            int idx = tid + i * 256;
            int row = idx >> 2, ch16 = idx & 3;
            const __half* src = W + (size_t)(n0 + row) * K + k0 + ch16 * 8;
            uint32_t dst = sa + (uint32_t)(HG_ASTF + row * HG_LD + ch16 * 8) * 2u;
            cp_async16(dst, src, 16u);
        }
    };

    load_stage(0, 0); CP_COMMIT();
    load_stage(1, 1); CP_COMMIT();

    for (int ch = 0; ch < nchunk; ch++) {
        int s = ch % 3;
        CP_WAIT1();
        __syncthreads();
        if (ch + 2 < nchunk) load_stage((ch + 2) % 3, ch + 2);
        CP_COMMIT();

        const __half* As = smh + s * HG_STF;
        const __half* Bs = As + HG_ASTF;
        const __half* ab = As + (wm * 64 + r) * HG_LD + 2 * c;
        const __half* bb = Bs + (wn * 32 + r) * HG_LD + 2 * c;

        #pragma unroll
        for (int ks = 0; ks < 2; ks++) {          // two k16 steps per chunk
            uint32_t af[4][4], bf[4][2];
            #pragma unroll
            for (int i = 0; i < 4; i++) {
                const __half* pa = ab + i * 16 * HG_LD + ks * 16;
                af[i][0] = ldh2(pa);
                af[i][1] = ldh2(pa + 8 * HG_LD);
                af[i][2] = ldh2(pa + 8);
                af[i][3] = ldh2(pa + 8 * HG_LD + 8);
            }
            #pragma unroll
            for (int j = 0; j < 4; j++) {
                const __half* pb = bb + j * 8 * HG_LD + ks * 16;
                bf[j][0] = ldh2(pb);
                bf[j][1] = ldh2(pb + 8);
            }
            #pragma unroll
            for (int i = 0; i < 4; i++)
                #pragma unroll
                for (int j = 0; j < 4; j++)
                    mma_f16(acc[i][j], af[i], bf[j]);
        }
    }

    // epilogue: element pair (row, 2c/2c+1) and (row+8, ...)
    #pragma unroll
    for (int i = 0; i < 4; i++) {
        int gr0 = m0 + wm * 64 + i * 16 + r;
        #pragma unroll
        for (int half_m = 0; half_m < 2; half_m++) {
            int gm = gr0 + half_m * 8;
            if (gm >= M) continue;
            #pragma unroll
            for (int j = 0; j < 4; j++) {
                int gn = n0 + wn * 32 + j * 8 + 2 * c;
                float2 b2 = *(const float2*)&bias[gn];
                float vx = acc[i][j][half_m * 2 + 0] + b2.x;
                float vy = acc[i][j][half_m * 2 + 1] + b2.y;
                if (MODE == 1) {
                    float2 r2 = *(const float2*)&RG[(size_t)gm * N + gn];
                    vx += r2.x; vy += r2.y;
                }
                if (MODE == 2) {
                    float2 g2 = *(const float2*)&RG[(size_t)gm * N + gn];
                    float sx = g2.x / (1.0f + __expf(-g2.x));
                    float sy = g2.y / (1.0f + __expf(-g2.y));
                    __half2 h = __floats2half2_rn(sx * vx, sy * vy);
                    *(__half2*)&((__half*)outp)[(size_t)gm * N + gn] = h;
                } else {
                    float2 o; o.x = vx; o.y = vy;
                    *(float2*)&((float*)outp)[(size_t)gm * N + gn] = o;
                }
            }
        }
    }
}

// ---------------------------------------------------------------------------
// LayerNorm: one block (256 threads) per row of 768. fp16 output.
// ---------------------------------------------------------------------------
__global__ void ln_kernel(const float* __restrict__ x,
                          const float* __restrict__ g,
                          const float* __restrict__ b,
                          __half* __restrict__ out)
{
    int row = blockIdx.x;
    int tid = threadIdx.x;
    int lane = tid & 31;
    int wid  = tid >> 5;
    const float* xr = x + (size_t)row * CC;

    float v0 = xr[tid];
    float v1 = xr[tid + 256];
    float v2 = xr[tid + 512];

    __shared__ float red[8];

    float s = v0 + v1 + v2;
    #pragma unroll
    for (int off = 16; off > 0; off >>= 1) s += __shfl_xor_sync(0xffffffffu, s, off);
    if (lane == 0) red[wid] = s;
    __syncthreads();
    float tot = red[0] + red[1] + red[2] + red[3] + red[4] + red[5] + red[6] + red[7];
    float mean = tot * (1.0f / (float)CC);
    __syncthreads();

    float d0 = v0 - mean, d1 = v1 - mean, d2 = v2 - mean;
    float sq = d0 * d0 + d1 * d1 + d2 * d2;
    #pragma unroll
    for (int off = 16; off > 0; off >>= 1) sq += __shfl_xor_sync(0xffffffffu, sq, off);
    if (lane == 0) red[wid] = sq;
    __syncthreads();
    float tot2 = red[0] + red[1] + red[2] + red[3] + red[4] + red[5] + red[6] + red[7];
    float var = tot2 * (1.0f / (float)CC);
    float rstd = rsqrtf(var + LN_EPS);

    __half* orow = out + (size_t)row * CC;
    orow[tid]       = __float2half(d0 * rstd * g[tid]       + b[tid]);
    orow[tid + 256] = __float2half(d1 * rstd * g[tid + 256] + b[tid + 256]);
    orow[tid + 512] = __float2half(d2 * rstd * g[tid + 512] + b[tid + 512]);
}

// ---------------------------------------------------------------------------
// RoPE in place (fp32 qkv; unchanged)
// ---------------------------------------------------------------------------
__global__ void rope_kernel(float* __restrict__ qkv,
                            const float* __restrict__ freqs)
{
    int idx = blockIdx.x * blockDim.x + threadIdx.x;
    if (idx >= MM * 768) return;
    int m   = idx / 768;
    int rem = idx % 768;
    int s   = rem / 384;
    int hr  = rem % 384;
    int h   = hr >> 5;
    int dd  = hr & 31;
    int n   = m % NN;

    size_t base = (size_t)m * C3 + s * CC + h * HD;
    float f1 = freqs[n * HD + dd];
    float f2 = freqs[n * HD + dd + 32];
    float c1, s1, c2, s2;
    sincosf(f1, &s1, &c1);
    sincosf(f2, &s2, &c2);
    float x1 = qkv[base + dd];
    float x2 = qkv[base + dd + 32];
    qkv[base + dd]      = x1 * c1 - x2 * s1;
    qkv[base + dd + 32] = x2 * c2 + x1 * s2;
}

// ---------------------------------------------------------------------------
// fp16 tensor-core flash attention. BQ=BKV=64, 8 warps (4m x 2n), warp tile
// 16x32, mma m16n8k16. Softmax fp32 in smem S; P staged fp16.
// Q/K/V fp16 tiles ld=72 halves; S fp32 ld=68. Scale folded into Q.
// ---------------------------------------------------------------------------
#define FH_LD 72
#define FH_TILE (64 * FH_LD)             // halves per fp16 tile
#define FS_LD 68
#define FA_SMEM (64 * FS_LD * 4 + 3 * 64 * 4 + 4 * FH_TILE * 2)  // 55040 B

__global__ void __launch_bounds__(256)
flash_f16_kernel(const float* __restrict__ qkv, __half* __restrict__ o)
{
    extern __shared__ char fsm[];
    float*  Ss    = (float*)fsm;                       // [q][kv] fp32
    float*  row_m = Ss + 64 * FS_LD;
    float*  row_l = row_m + 64;
    float*  row_s = row_l + 64;
    __half* Qs    = (__half*)(row_s + 64);             // [q][d]
    __half* Ks    = Qs + FH_TILE;                      // [kv][d]
    __half* Vt    = Ks + FH_TILE;                      // [d][kv]
    __half* Ps    = Vt + FH_TILE;                      // [q][kv] fp16

    const int tid  = threadIdx.x;
    const int warp = tid >> 5;
    const int lane = tid & 31;
    const int wm = warp & 3;             // m strip *16
    const int wn = warp >> 2;            // n strip *32
    const int fr = lane >> 2;            // 0..7
    const int fc = lane & 3;             // 0..3
    const int q0 = blockIdx.x * 64;
    const int b  = blockIdx.y / HH;
    const int h  = blockIdx.y % HH;
    const size_t headoff = (size_t)h * HD;

    if (tid < 64) { row_m[tid] = -INFINITY; row_l[tid] = 0.0f; }

    // Q tile: scale by 0.125, convert to fp16
    #pragma unroll
    for (int i = 0; i < 4; i++) {
        int idx = tid + i * 256;
        int r = idx >> 4, c4 = idx & 15;
        int n = q0 + r;
        float4 v = make_float4(0.f, 0.f, 0.f, 0.f);
        if (n < NN) v = *(const float4*)&qkv[(size_t)(b * NN + n) * C3 + headoff + c4 * 4];
        __half2 h0 = __floats2half2_rn(v.x * 0.125f, v.y * 0.125f);
        __half2 h1 = __floats2half2_rn(v.z * 0.125f, v.w * 0.125f);
        *(__half2*)&Qs[r * FH_LD + c4 * 4]     = h0;
        *(__half2*)&Qs[r * FH_LD + c4 * 4 + 2] = h1;
    }

    float oacc[4][4];
    #pragma unroll
    for (int j = 0; j < 4; j++)
        #pragma unroll
        for (int e = 0; e < 4; e++) oacc[j][e] = 0.0f;

    const int ntiles = (NN + 63) / 64;   // 22

    for (int t = 0; t < ntiles; t++) {
        const int kv0 = t * 64;
        __syncthreads();                 // previous Ks/Vt/Ps readers done

        // K tile [kv][d] + V transposed [d][kv], fp16
        #pragma unroll
        for (int i = 0; i < 4; i++) {
            int idx = tid + i * 256;
            int r = idx >> 4, c4 = idx & 15;
            int n = kv0 + r;
            float4 kv = make_float4(0.f, 0.f, 0.f, 0.f);
            float4 vv = make_float4(0.f, 0.f, 0.f, 0.f);
            if (n < NN) {
                size_t base = (size_t)(b * NN + n) * C3 + headoff;
                kv = *(const float4*)&qkv[base + CC + c4 * 4];
                vv = *(const float4*)&qkv[base + 2 * CC + c4 * 4];
            }
            __half2 k0h = __floats2half2_rn(kv.x, kv.y);
            __half2 k1h = __floats2half2_rn(kv.z, kv.w);
            *(__half2*)&Ks[r * FH_LD + c4 * 4]     = k0h;
            *(__half2*)&Ks[r * FH_LD + c4 * 4 + 2] = k1h;
            int d = c4 * 4;
            Vt[(d + 0) * FH_LD + r] = __float2half(vv.x);
            Vt[(d + 1) * FH_LD + r] = __float2half(vv.y);
            Vt[(d + 2) * FH_LD + r] = __float2half(vv.z);
            Vt[(d + 3) * FH_LD + r] = __float2half(vv.w);
        }
        __syncthreads();

        // S = Q @ K^T (warp tile 16x32; 4 k16 steps over d=64)
        float sacc[4][4];
        #pragma unroll
        for (int j = 0; j < 4; j++)
            #pragma unroll
            for (int e = 0; e < 4; e++) sacc[j][e] = 0.0f;
        {
            const __half* ab = Qs + (wm * 16 + fr) * FH_LD + 2 * fc;
            const __half* bb = Ks + (wn * 32 + fr) * FH_LD + 2 * fc;
            #pragma unroll
            for (int ks = 0; ks < 4; ks++) {
                uint32_t af[4], bf[2];
                const __half* pa = ab + ks * 16;
                af[0] = ldh2(pa);
                af[1] = ldh2(pa + 8 * FH_LD);
                af[2] = ldh2(pa + 8);
                af[3] = ldh2(pa + 8 * FH_LD + 8);
                #pragma unroll
                for (int j = 0; j < 4; j++) {
                    const __half* pb = bb + j * 8 * FH_LD + ks * 16;
                    bf[0] = ldh2(pb);
                    bf[1] = ldh2(pb + 8);
                    mma_f16(sacc[j], af, bf);
                }
            }
        }
        // write S fragments (fp32, row-major)
        #pragma unroll
        for (int j = 0; j < 4; j++) {
            float* d0 = Ss + (wm * 16 + fr) * FS_LD + wn * 32 + j * 8 + 2 * fc;
            d0[0] = sacc[j][0]; d0[1] = sacc[j][1];
            float* d1 = d0 + 8 * FS_LD;
            d1[0] = sacc[j][2]; d1[1] = sacc[j][3];
        }
        __syncthreads();

        // online softmax: 4 lanes per row, 16 cols each; P -> fp16 tile
        {
            int r = tid >> 2;
            int part = tid & 3;
            float pv[16];
            #pragma unroll
            for (int j4 = 0; j4 < 4; j4++)
                *(float4*)&pv[j4 * 4] = *(const float4*)&Ss[r * FS_LD + part * 16 + j4 * 4];
            if (kv0 + 64 > NN) {         // key mask, last tile only
                #pragma unroll
                for (int j = 0; j < 16; j++)
                    if (kv0 + part * 16 + j >= NN) pv[j] = -INFINITY;
            }
            float lmax = pv[0];
            #pragma unroll
            for (int j = 1; j < 16; j++) lmax = fmaxf(lmax, pv[j]);
            lmax = fmaxf(lmax, __shfl_xor_sync(0xffffffffu, lmax, 1));
            lmax = fmaxf(lmax, __shfl_xor_sync(0xffffffffu, lmax, 2));
            float m_old = row_m[r];
            float m_new = fmaxf(m_old, lmax);
            float lsum = 0.0f;
            #pragma unroll
            for (int j = 0; j < 16; j++) {
                pv[j] = __expf(pv[j] - m_new);   // exp(-inf)=0 handles mask
                lsum += pv[j];
            }
            lsum += __shfl_xor_sync(0xffffffffu, lsum, 1);
            lsum += __shfl_xor_sync(0xffffffffu, lsum, 2);
            float sc = __expf(m_old - m_new);    // m_old=-inf -> 0
            if (part == 0) {
                row_s[r] = sc;
                row_m[r] = m_new;
                row_l[r] = row_l[r] * sc + lsum;
            }
            #pragma unroll
            for (int j4 = 0; j4 < 4; j4++) {
                __half2 h0 = __floats2half2_rn(pv[j4 * 4 + 0], pv[j4 * 4 + 1]);
                __half2 h1 = __floats2half2_rn(pv[j4 * 4 + 2], pv[j4 * 4 + 3]);
                *(__half2*)&Ps[r * FH_LD + part * 16 + j4 * 4]     = h0;
                *(__half2*)&Ps[r * FH_LD + part * 16 + j4 * 4 + 2] = h1;
            }
        }
        __syncthreads();                 // P + row_s visible

        // rescale O and accumulate P @ V (4 k16 steps over kv=64)
        {
            float rs0 = row_s[wm * 16 + fr];
            float rs1 = row_s[wm * 16 + fr + 8];
            #pragma unroll
            for (int j = 0; j < 4; j++) {
                oacc[j][0] *= rs0; oacc[j][1] *= rs0;
                oacc[j][2] *= rs1; oacc[j][3] *= rs1;
            }
            const __half* ap = Ps + (wm * 16 + fr) * FH_LD + 2 * fc;
            const __half* bp = Vt + (wn * 32 + fr) * FH_LD + 2 * fc;
            #pragma unroll
            for (int ks = 0; ks < 4; ks++) {
                uint32_t af[4], bf[2];
                const __half* pa = ap + ks * 16;
                af[0] = ldh2(pa);
                af[1] = ldh2(pa + 8 * FH_LD);
                af[2] = ldh2(pa + 8);
                af[3] = ldh2(pa + 8 * FH_LD + 8);
                #pragma unroll
                for (int j = 0; j < 4; j++) {
                    const __half* pb = bp + j * 8 * FH_LD + ks * 16;
                    bf[0] = ldh2(pb);
                    bf[1] = ldh2(pb + 8);
                    mma_f16(oacc[j], af, bf);
                }
            }
        }
    }

    // normalize + store fp16 (feeds proj GEMM)
    {
        int r0 = wm * 16 + fr;
        float inv0 = 1.0f / row_l[r0];
        float inv1 = 1.0f / row_l[r0 + 8];
        int n0g = q0 + r0;
        int n1g = n0g + 8;
        #pragma unroll
        for (int j = 0; j < 4; j++) {
            size_t col = headoff + wn * 32 + j * 8 + 2 * fc;
            if (n0g < NN) {
                __half2 ov = __floats2half2_rn(oacc[j][0] * inv0, oacc[j][1] * inv0);
                *(__half2*)&o[(size_t)(b * NN + n0g) * CC + col] = ov;
            }
            if (n1g < NN) {
                __half2 ov = __floats2half2_rn(oacc[j][2] * inv1, oacc[j][3] * inv1);
                *(__half2*)&o[(size_t)(b * NN + n1g) * CC + col] = ov;
            }
        }
    }
}

// ---------------------------------------------------------------------------
// Launch
// ---------------------------------------------------------------------------
static inline void conv_h(const float* in, __half* out, int elems) {
    int n4 = elems / 4;
    f2h_kernel<<<(n4 + 255) / 256, 256>>>(in, out, n4);
}

extern "C" void kernel_launch(void* const* d_in, const int* in_sizes, int n_in,
                              void* d_out, int out_size)
{
    const float* x      = (const float*)d_in[0];
    const float* freqs  = (const float*)d_in[1];
    const float* ln1_g  = (const float*)d_in[2];
    const float* ln1_b  = (const float*)d_in[3];
    const float* qkv_w  = (const float*)d_in[4];
    const float* qkv_b  = (const float*)d_in[5];
    const float* proj_w = (const float*)d_in[6];
    const float* proj_b = (const float*)d_in[7];
    const float* ln2_g  = (const float*)d_in[8];
    const float* ln2_b  = (const float*)d_in[9];
    const float* w1     = (const float*)d_in[10];
    const float* b1     = (const float*)d_in[11];
    const float* w2     = (const float*)d_in[12];
    const float* b2     = (const float*)d_in[13];
    const float* w3     = (const float*)d_in[14];
    const float* b3     = (const float*)d_in[15];
    float* out = (float*)d_out;

    __half *h_buf, *attn_buf, *hid_buf, *wh;
    float  *qkv_buf, *x1_buf;
    cudaGetSymbolAddress((void**)&h_buf, g_h);
    cudaGetSymbolAddress((void**)&qkv_buf, g_qkv);
    cudaGetSymbolAddress((void**)&attn_buf, g_attn);
    cudaGetSymbolAddress((void**)&x1_buf, g_x1);
    cudaGetSymbolAddress((void**)&hid_buf, g_hid);
    cudaGetSymbolAddress((void**)&wh, g_wh);

    cudaFuncSetAttribute(gemm_f16<0>,
                         cudaFuncAttributeMaxDynamicSharedMemorySize, HG_SMEM);
    cudaFuncSetAttribute(gemm_f16<1>,
                         cudaFuncAttributeMaxDynamicSharedMemorySize, HG_SMEM);
    cudaFuncSetAttribute(gemm_f16<2>,
                         cudaFuncAttributeMaxDynamicSharedMemorySize, HG_SMEM);
    cudaFuncSetAttribute(flash_f16_kernel,
                         cudaFuncAttributeMaxDynamicSharedMemorySize, FA_SMEM);

    const int mblocks = (MM + 127) / 128;   // 86

    // 0) weights -> fp16
    conv_h(qkv_w,  wh + WH_QKV,  C3 * CC);
    conv_h(proj_w, wh + WH_PROJ, CC * CC);
    conv_h(w1,     wh + WH_W1,   HID * CC);
    conv_h(w2,     wh + WH_W2,   HID * CC);
    conv_h(w3,     wh + WH_W3,   CC * HID);

    // 1) LN1 -> fp16
    ln_kernel<<<MM, 256>>>(x, ln1_g, ln1_b, h_buf);

    // 2) QKV GEMM -> fp32 (rope needs fp32)
    gemm_f16<0><<<dim3(C3 / 128, mblocks), 256, HG_SMEM>>>(
        h_buf, wh + WH_QKV, qkv_b, nullptr, qkv_buf, MM, C3, CC);

    // 3) RoPE in place
    {
        int total = MM * 768;
        rope_kernel<<<(total + 255) / 256, 256>>>(qkv_buf, freqs);
    }

    // 4) Flash attention (fp16 tensor cores) -> fp16
    {
        dim3 grid((NN + 63) / 64, BB * HH);   // (22, 96)
        flash_f16_kernel<<<grid, 256, FA_SMEM>>>(qkv_buf, attn_buf);
    }

    // 5) proj GEMM + residual(x) -> out (fp32)
    gemm_f16<1><<<dim3(CC / 128, mblocks), 256, HG_SMEM>>>(
        attn_buf, wh + WH_PROJ, proj_b, x, out, MM, CC, CC);

    // 6) LN2 -> fp16
    ln_kernel<<<MM, 256>>>(out, ln2_g, ln2_b, h_buf);

    // 7) x1 GEMM -> fp32
    gemm_f16<0><<<dim3(HID / 128, mblocks), 256, HG_SMEM>>>(
        h_buf, wh + WH_W1, b1, nullptr, x1_buf, MM, HID, CC);

    // 8) x2 GEMM with fused SwiGLU -> hid (fp16)
    gemm_f16<2><<<dim3(HID / 128, mblocks), 256, HG_SMEM>>>(
        h_buf, wh + WH_W2, b2, x1_buf, hid_buf, MM, HID, CC);

    // 9) mlp GEMM + residual -> out (fp32)
    gemm_f16<1><<<dim3(CC / 128, mblocks), 256, HG_SMEM>>>(
        hid_buf, wh + WH_W3, b3, out, out, MM, CC, HID);
}

// round 14
// speedup vs baseline: 4.9389x; 1.1330x over previous
#include <cuda_runtime.h>
#include <cuda_fp16.h>
#include <math.h>
#include <stdint.h>

// ---------------------------------------------------------------------------
// Problem constants
// ---------------------------------------------------------------------------
#define BB   8
#define NN   1374
#define CC   768
#define HH   12
#define HD   64
#define C3   2304
#define HID  3072
#define MM   (BB * NN)          // 10992 rows
#define LN_EPS 1e-5f

// ---------------------------------------------------------------------------
// Scratch (device globals; no allocations allowed)
// ---------------------------------------------------------------------------
__device__ __half g_h[MM * CC];         // LN output (fp16)
__device__ __half g_qkv[MM * C3];       // QKV output (fp16, RoPE in place)
__device__ __half g_attn[MM * CC];      // attention output (fp16)
__device__ __half g_x1[MM * HID];       // MLP x1 (fp16, read by fused silu)
__device__ __half g_hid[MM * HID];      // silu(x1)*x2 (fp16)
// fp16 weight copies (element offsets)
#define WH_QKV  0
#define WH_PROJ 1769472
#define WH_W1   2359296
#define WH_W2   4718592
#define WH_W3   7077888
#define WH_TOT  9437184
__device__ __half g_wh[WH_TOT];

// ---------------------------------------------------------------------------
// Helpers
// ---------------------------------------------------------------------------
__device__ __forceinline__ uint32_t smem_u32(const void* p) {
    uint32_t a;
    asm("{ .reg .u64 t; cvta.to.shared.u64 t, %1; cvt.u32.u64 %0, t; }"
        : "=r"(a) : "l"(p));
    return a;
}
__device__ __forceinline__ void cp_async16(uint32_t dst, const void* src, uint32_t sz) {
    asm volatile("cp.async.cg.shared.global [%0], [%1], 16, %2;"
                 :: "r"(dst), "l"(src), "r"(sz));
}
#define CP_COMMIT() asm volatile("cp.async.commit_group;" ::: "memory")
#define CP_WAIT1()  asm volatile("cp.async.wait_group 1;" ::: "memory")
#define CP_WAIT0()  asm volatile("cp.async.wait_group 0;" ::: "memory")

__device__ __forceinline__ uint32_t ldh2(const __half* p) {
    return *(const uint32_t*)p;          // aligned half2 load
}
__device__ __forceinline__ void mma_f16(float* d, const uint32_t* a, const uint32_t* b) {
    asm volatile(
        "mma.sync.aligned.m16n8k16.row.col.f32.f16.f16.f32 "
        "{%0,%1,%2,%3}, {%4,%5,%6,%7}, {%8,%9}, {%0,%1,%2,%3};"
        : "+f"(d[0]), "+f"(d[1]), "+f"(d[2]), "+f"(d[3])
        : "r"(a[0]), "r"(a[1]), "r"(a[2]), "r"(a[3]), "r"(b[0]), "r"(b[1]));
}

// ---------------------------------------------------------------------------
// fp32 -> fp16 conversion (weights)
// ---------------------------------------------------------------------------
__global__ void f2h_kernel(const float* __restrict__ in,
                           __half* __restrict__ out, int n4)
{
    int idx = blockIdx.x * blockDim.x + threadIdx.x;
    if (idx >= n4) return;
    float4 v = ((const float4*)in)[idx];
    ((__half2*)out)[idx * 2]     = __floats2half2_rn(v.x, v.y);
    ((__half2*)out)[idx * 2 + 1] = __floats2half2_rn(v.z, v.w);
}

// ---------------------------------------------------------------------------
// fp16 tensor-core NT GEMM.
// MODE 0: out fp32 + bias.           MODE 1: out fp32 + bias + residual R (fp32).
// MODE 2: fused SwiGLU — G fp16 x1, out half = silu(G)*(acc+bias).
// MODE 3: out fp16 + bias.
// BM=BN=128, BK=32 halves, 8 warps (2m x 4n), warp tile 64x32, 3-stage cp.async.
// ---------------------------------------------------------------------------
#define HG_LD   40
#define HG_ASTF (128 * HG_LD)
#define HG_STF  (2 * HG_ASTF)
#define HG_SMEM (3 * HG_STF * 2)         // 61440 bytes

template <int MODE>
__global__ void __launch_bounds__(256, 2)
gemm_f16(const __half* __restrict__ A, const __half* __restrict__ W,
         const float* __restrict__ bias, const void* __restrict__ RG,
         void* __restrict__ outp, int M, int N, int K)
{
    extern __shared__ __half smh[];
    const uint32_t sb = smem_u32(smh);
    const int tid  = threadIdx.x;
    const int warp = tid >> 5;
    const int lane = tid & 31;
    const int wm = warp >> 2;
    const int wn = warp & 3;
    const int r = lane >> 2;
    const int c = lane & 3;
    const int m0 = blockIdx.y * 128;
    const int n0 = blockIdx.x * 128;

    float acc[4][4][4];
    #pragma unroll
    for (int i = 0; i < 4; i++)
        #pragma unroll
        for (int j = 0; j < 4; j++)
            #pragma unroll
            for (int e = 0; e < 4; e++) acc[i][j][e] = 0.0f;

    const int nchunk = K >> 5;

    auto load_stage = [&](int s, int ch) {
        const int k0 = ch << 5;
        const uint32_t sa = sb + (uint32_t)(s * HG_STF) * 2u;
        #pragma unroll
        for (int i = 0; i < 2; i++) {
            int idx = tid + i * 256;
            int row = idx >> 2, ch16 = idx & 3;
            int gm = m0 + row;
            int gms = gm < M ? gm : M - 1;
            const __half* src = A + (size_t)gms * K + k0 + ch16 * 8;
            uint32_t dst = sa + (uint32_t)(row * HG_LD + ch16 * 8) * 2u;
            cp_async16(dst, src, gm < M ? 16u : 0u);
        }
        #pragma unroll
        for (int i = 0; i < 2; i++) {
            int idx = tid + i * 256;
            int row = idx >> 2, ch16 = idx & 3;
            const __half* src = W + (size_t)(n0 + row) * K + k0 + ch16 * 8;
            uint32_t dst = sa + (uint32_t)(HG_ASTF + row * HG_LD + ch16 * 8) * 2u;
            cp_async16(dst, src, 16u);
        }
    };

    load_stage(0, 0); CP_COMMIT();
    load_stage(1, 1); CP_COMMIT();

    for (int ch = 0; ch < nchunk; ch++) {
        int s = ch % 3;
        CP_WAIT1();
        __syncthreads();
        if (ch + 2 < nchunk) load_stage((ch + 2) % 3, ch + 2);
        CP_COMMIT();

        const __half* As = smh + s * HG_STF;
        const __half* Bs = As + HG_ASTF;
        const __half* ab = As + (wm * 64 + r) * HG_LD + 2 * c;
        const __half* bb = Bs + (wn * 32 + r) * HG_LD + 2 * c;

        #pragma unroll
        for (int ks = 0; ks < 2; ks++) {
            uint32_t af[4][4], bf[4][2];
            #pragma unroll
            for (int i = 0; i < 4; i++) {
                const __half* pa = ab + i * 16 * HG_LD + ks * 16;
                af[i][0] = ldh2(pa);
                af[i][1] = ldh2(pa + 8 * HG_LD);
                af[i][2] = ldh2(pa + 8);
                af[i][3] = ldh2(pa + 8 * HG_LD + 8);
            }
            #pragma unroll
            for (int j = 0; j < 4; j++) {
                const __half* pb = bb + j * 8 * HG_LD + ks * 16;
                bf[j][0] = ldh2(pb);
                bf[j][1] = ldh2(pb + 8);
            }
            #pragma unroll
            for (int i = 0; i < 4; i++)
                #pragma unroll
                for (int j = 0; j < 4; j++)
                    mma_f16(acc[i][j], af[i], bf[j]);
        }
    }

    #pragma unroll
    for (int i = 0; i < 4; i++) {
        int gr0 = m0 + wm * 64 + i * 16 + r;
        #pragma unroll
        for (int half_m = 0; half_m < 2; half_m++) {
            int gm = gr0 + half_m * 8;
            if (gm >= M) continue;
            #pragma unroll
            for (int j = 0; j < 4; j++) {
                int gn = n0 + wn * 32 + j * 8 + 2 * c;
                float2 b2 = *(const float2*)&bias[gn];
                float vx = acc[i][j][half_m * 2 + 0] + b2.x;
                float vy = acc[i][j][half_m * 2 + 1] + b2.y;
                if (MODE == 0) {
                    float2 o; o.x = vx; o.y = vy;
                    *(float2*)&((float*)outp)[(size_t)gm * N + gn] = o;
                } else if (MODE == 1) {
                    float2 r2 = *(const float2*)&((const float*)RG)[(size_t)gm * N + gn];
                    float2 o; o.x = vx + r2.x; o.y = vy + r2.y;
                    *(float2*)&((float*)outp)[(size_t)gm * N + gn] = o;
                } else if (MODE == 2) {
                    __half2 g2h = *(const __half2*)&((const __half*)RG)[(size_t)gm * N + gn];
                    float2 g2 = __half22float2(g2h);
                    float sx = g2.x / (1.0f + __expf(-g2.x));
                    float sy = g2.y / (1.0f + __expf(-g2.y));
                    *(__half2*)&((__half*)outp)[(size_t)gm * N + gn] =
                        __floats2half2_rn(sx * vx, sy * vy);
                } else {
                    *(__half2*)&((__half*)outp)[(size_t)gm * N + gn] =
                        __floats2half2_rn(vx, vy);
                }
            }
        }
    }
}

// ---------------------------------------------------------------------------
// LayerNorm: one block (256 threads) per row of 768. fp16 output.
// ---------------------------------------------------------------------------
__global__ void ln_kernel(const float* __restrict__ x,
                          const float* __restrict__ g,
                          const float* __restrict__ b,
                          __half* __restrict__ out)
{
    int row = blockIdx.x;
    int tid = threadIdx.x;
    int lane = tid & 31;
    int wid  = tid >> 5;
    const float* xr = x + (size_t)row * CC;

    float v0 = xr[tid];
    float v1 = xr[tid + 256];
    float v2 = xr[tid + 512];

    __shared__ float red[8];

    float s = v0 + v1 + v2;
    #pragma unroll
    for (int off = 16; off > 0; off >>= 1) s += __shfl_xor_sync(0xffffffffu, s, off);
    if (lane == 0) red[wid] = s;
    __syncthreads();
    float tot = red[0] + red[1] + red[2] + red[3] + red[4] + red[5] + red[6] + red[7];
    float mean = tot * (1.0f / (float)CC);
    __syncthreads();

    float d0 = v0 - mean, d1 = v1 - mean, d2 = v2 - mean;
    float sq = d0 * d0 + d1 * d1 + d2 * d2;
    #pragma unroll
    for (int off = 16; off > 0; off >>= 1) sq += __shfl_xor_sync(0xffffffffu, sq, off);
    if (lane == 0) red[wid] = sq;
    __syncthreads();
    float tot2 = red[0] + red[1] + red[2] + red[3] + red[4] + red[5] + red[6] + red[7];
    float var = tot2 * (1.0f / (float)CC);
    float rstd = rsqrtf(var + LN_EPS);

    __half* orow = out + (size_t)row * CC;
    orow[tid]       = __float2half(d0 * rstd * g[tid]       + b[tid]);
    orow[tid + 256] = __float2half(d1 * rstd * g[tid + 256] + b[tid + 256]);
    orow[tid + 512] = __float2half(d2 * rstd * g[tid + 512] + b[tid + 512]);
}

// ---------------------------------------------------------------------------
// RoPE in place on fp16 qkv. One block per token row; fast sincos.
// qkv row: [q 768 | k 768 | v 768], per head pairs (dd, dd+32).
// ---------------------------------------------------------------------------
__global__ void rope_kernel(__half* __restrict__ qkv,
                            const float* __restrict__ freqs)
{
    const int m = blockIdx.x;
    const int n = m % NN;
    const size_t mbase = (size_t)m * C3;
    for (int e = threadIdx.x; e < 768; e += 256) {
        int s  = e >= 384;
        int hr = e - s * 384;
        int h  = hr >> 5;
        int dd = hr & 31;
        size_t base = mbase + s * CC + h * HD;
        float f1 = freqs[n * HD + dd];
        float f2 = freqs[n * HD + dd + 32];
        float s1, c1, s2, c2;
        __sincosf(f1, &s1, &c1);
        __sincosf(f2, &s2, &c2);
        float x1 = __half2float(qkv[base + dd]);
        float x2 = __half2float(qkv[base + dd + 32]);
        qkv[base + dd]      = __float2half(x1 * c1 - x2 * s1);
        qkv[base + dd + 32] = __float2half(x2 * c2 + x1 * s2);
    }
}

// ---------------------------------------------------------------------------
// fp16 flash attention v2. BQ=128, BKV=64, 8 warps; warp w owns q-strip
// w*16..w*16+15 (full 64 kv / 64 d). mma m16n8k16. Q/K loads via cp.async
// (qkv already fp16); V transposed manually. Scale 0.125 applied in softmax.
// ---------------------------------------------------------------------------
#define FH_LD 72
#define FS_LD 68
#define FA_SMEM ((128 * FS_LD + 3 * 128) * 4 + \
                 (128 * FH_LD + 64 * FH_LD + 64 * FH_LD + 128 * FH_LD) * 2) // 91648

__global__ void __launch_bounds__(256)
flash_f16_kernel(const __half* __restrict__ qkv, __half* __restrict__ o)
{
    extern __shared__ char fsm[];
    float*  Ss    = (float*)fsm;                 // [128][FS_LD] fp32
    float*  row_m = Ss + 128 * FS_LD;
    float*  row_l = row_m + 128;
    float*  row_s = row_l + 128;
    __half* Qs    = (__half*)(row_s + 128);      // [128][FH_LD]
    __half* Ks    = Qs + 128 * FH_LD;            // [64][FH_LD]
    __half* Vt    = Ks + 64 * FH_LD;             // [64][FH_LD] (d-major)
    __half* Ps    = Vt + 64 * FH_LD;             // [128][FH_LD] fp16

    const uint32_t sbq = smem_u32(Qs);
    const uint32_t sbk = smem_u32(Ks);
    const int tid  = threadIdx.x;
    const int warp = tid >> 5;
    const int lane = tid & 31;
    const int fr = lane >> 2;            // 0..7
    const int fc = lane & 3;             // 0..3
    const int q0 = blockIdx.x * 128;
    const int b  = blockIdx.y / HH;
    const int h  = blockIdx.y % HH;
    const size_t headoff = (size_t)h * HD;

    if (tid < 128) { row_m[tid] = -INFINITY; row_l[tid] = 0.0f; }

    // Q tile: cp.async fp16 copy (128 rows x 8 x 16B)
    #pragma unroll
    for (int i = 0; i < 4; i++) {
        int idx = tid + i * 256;
        int r = idx >> 3, c8 = idx & 7;
        int n = q0 + r;
        int ns = n < NN ? n : NN - 1;
        const __half* src = qkv + (size_t)(b * NN + ns) * C3 + headoff + c8 * 8;
        cp_async16(sbq + (uint32_t)(r * FH_LD + c8 * 8) * 2u, src, n < NN ? 16u : 0u);
    }
    CP_COMMIT();

    float oacc[8][4];
    #pragma unroll
    for (int j = 0; j < 8; j++)
        #pragma unroll
        for (int e = 0; e < 4; e++) oacc[j][e] = 0.0f;

    const int ntiles = (NN + 63) / 64;   // 22

    for (int t = 0; t < ntiles; t++) {
        const int kv0 = t * 64;
        __syncthreads();                 // previous Ks/Vt/Ps readers done

        // K tile via cp.async (64 rows x 8 x 16B); V transposed manually
        #pragma unroll
        for (int i = 0; i < 2; i++) {
            int idx = tid + i * 256;
            int r = idx >> 3, c8 = idx & 7;
            int n = kv0 + r;
            int ns = n < NN ? n : NN - 1;
            const __half* src = qkv + (size_t)(b * NN + ns) * C3 + CC + headoff + c8 * 8;
            cp_async16(sbk + (uint32_t)(r * FH_LD + c8 * 8) * 2u, src, n < NN ? 16u : 0u);
        }
        CP_COMMIT();
        #pragma unroll
        for (int i = 0; i < 2; i++) {
            int idx = tid + i * 256;
            int r = idx >> 3, c8 = idx & 7;
            int n = kv0 + r;
            __half hv[8];
            if (n < NN) {
                *(uint4*)hv = *(const uint4*)(qkv + (size_t)(b * NN + n) * C3
                                              + 2 * CC + headoff + c8 * 8);
            } else {
                #pragma unroll
                for (int e2 = 0; e2 < 8; e2++) hv[e2] = __float2half(0.0f);
            }
            #pragma unroll
            for (int e2 = 0; e2 < 8; e2++)
                Vt[(c8 * 8 + e2) * FH_LD + r] = hv[e2];
        }
        CP_WAIT0();
        __syncthreads();

        // S = Q @ K^T : warp tile 16(q) x 64(kv); 4 k16 steps over d
        float sacc[8][4];
        #pragma unroll
        for (int j = 0; j < 8; j++)
            #pragma unroll
            for (int e = 0; e < 4; e++) sacc[j][e] = 0.0f;
        {
            const __half* ab = Qs + (warp * 16 + fr) * FH_LD + 2 * fc;
            const __half* bb = Ks + fr * FH_LD + 2 * fc;
            #pragma unroll
            for (int ks = 0; ks < 4; ks++) {
                uint32_t af[4], bf[2];
                const __half* pa = ab + ks * 16;
                af[0] = ldh2(pa);
                af[1] = ldh2(pa + 8 * FH_LD);
                af[2] = ldh2(pa + 8);
                af[3] = ldh2(pa + 8 * FH_LD + 8);
                #pragma unroll
                for (int j = 0; j < 8; j++) {
                    const __half* pb = bb + j * 8 * FH_LD + ks * 16;
                    bf[0] = ldh2(pb);
                    bf[1] = ldh2(pb + 8);
                    mma_f16(sacc[j], af, bf);
                }
            }
        }
        // write S (fp32)
        #pragma unroll
        for (int j = 0; j < 8; j++) {
            float* d0 = Ss + (warp * 16 + fr) * FS_LD + j * 8 + 2 * fc;
            d0[0] = sacc[j][0]; d0[1] = sacc[j][1];
            float* d1 = d0 + 8 * FS_LD;
            d1[0] = sacc[j][2]; d1[1] = sacc[j][3];
        }
        __syncthreads();

        // online softmax over 128 rows (two 64-row halves); scale here
        #pragma unroll
        for (int half = 0; half < 2; half++) {
            int r = (tid >> 2) + half * 64;
            int part = tid & 3;
            float pv[16];
            #pragma unroll
            for (int j4 = 0; j4 < 4; j4++) {
                float4 v4 = *(const float4*)&Ss[r * FS_LD + part * 16 + j4 * 4];
                pv[j4*4+0] = v4.x * 0.125f; pv[j4*4+1] = v4.y * 0.125f;
                pv[j4*4+2] = v4.z * 0.125f; pv[j4*4+3] = v4.w * 0.125f;
            }
            if (kv0 + 64 > NN) {
                #pragma unroll
                for (int j = 0; j < 16; j++)
                    if (kv0 + part * 16 + j >= NN) pv[j] = -INFINITY;
            }
            float lmax = pv[0];
            #pragma unroll
            for (int j = 1; j < 16; j++) lmax = fmaxf(lmax, pv[j]);
            lmax = fmaxf(lmax, __shfl_xor_sync(0xffffffffu, lmax, 1));
            lmax = fmaxf(lmax, __shfl_xor_sync(0xffffffffu, lmax, 2));
            float m_old = row_m[r];
            float m_new = fmaxf(m_old, lmax);
            float lsum = 0.0f;
            #pragma unroll
            for (int j = 0; j < 16; j++) {
                pv[j] = __expf(pv[j] - m_new);
                lsum += pv[j];
            }
            lsum += __shfl_xor_sync(0xffffffffu, lsum, 1);
            lsum += __shfl_xor_sync(0xffffffffu, lsum, 2);
            float sc = __expf(m_old - m_new);
            if (part == 0) {
                row_s[r] = sc;
                row_m[r] = m_new;
                row_l[r] = row_l[r] * sc + lsum;
            }
            #pragma unroll
            for (int j4 = 0; j4 < 4; j4++) {
                *(__half2*)&Ps[r * FH_LD + part * 16 + j4 * 4] =
                    __floats2half2_rn(pv[j4 * 4 + 0], pv[j4 * 4 + 1]);
                *(__half2*)&Ps[r * FH_LD + part * 16 + j4 * 4 + 2] =
                    __floats2half2_rn(pv[j4 * 4 + 2], pv[j4 * 4 + 3]);
            }
        }
        __syncthreads();

        // rescale O and accumulate P @ V : warp tile 16(q) x 64(d), k over kv
        {
            float rs0 = row_s[warp * 16 + fr];
            float rs1 = row_s[warp * 16 + fr + 8];
            #pragma unroll
            for (int j = 0; j < 8; j++) {
                oacc[j][0] *= rs0; oacc[j][1] *= rs0;
                oacc[j][2] *= rs1; oacc[j][3] *= rs1;
            }
            const __half* ap = Ps + (warp * 16 + fr) * FH_LD + 2 * fc;
            const __half* bp = Vt + fr * FH_LD + 2 * fc;
            #pragma unroll
            for (int ks = 0; ks < 4; ks++) {
                uint32_t af[4], bf[2];
                const __half* pa = ap + ks * 16;
                af[0] = ldh2(pa);
                af[1] = ldh2(pa + 8 * FH_LD);
                af[2] = ldh2(pa + 8);
                af[3] = ldh2(pa + 8 * FH_LD + 8);
                #pragma unroll
                for (int j = 0; j < 8; j++) {
                    const __half* pb = bp + j * 8 * FH_LD + ks * 16;
                    bf[0] = ldh2(pb);
                    bf[1] = ldh2(pb + 8);
                    mma_f16(oacc[j], af, bf);
                }
            }
        }
    }

    // normalize + store fp16
    {
        int r0 = warp * 16 + fr;
        float inv0 = 1.0f / row_l[r0];
        float inv1 = 1.0f / row_l[r0 + 8];
        int n0g = q0 + r0;
        int n1g = n0g + 8;
        #pragma unroll
        for (int j = 0; j < 8; j++) {
            size_t col = headoff + j * 8 + 2 * fc;
            if (n0g < NN) {
                *(__half2*)&o[(size_t)(b * NN + n0g) * CC + col] =
                    __floats2half2_rn(oacc[j][0] * inv0, oacc[j][1] * inv0);
            }
            if (n1g < NN) {
                *(__half2*)&o[(size_t)(b * NN + n1g) * CC + col] =
                    __floats2half2_rn(oacc[j][2] * inv1, oacc[j][3] * inv1);
            }
        }
    }
}

// ---------------------------------------------------------------------------
// Launch
// ---------------------------------------------------------------------------
static inline void conv_h(const float* in, __half* out, int elems) {
    int n4 = elems / 4;
    f2h_kernel<<<(n4 + 255) / 256, 256>>>(in, out, n4);
}

extern "C" void kernel_launch(void* const* d_in, const int* in_sizes, int n_in,
                              void* d_out, int out_size)
{
    const float* x      = (const float*)d_in[0];
    const float* freqs  = (const float*)d_in[1];
    const float* ln1_g  = (const float*)d_in[2];
    const float* ln1_b  = (const float*)d_in[3];
    const float* qkv_w  = (const float*)d_in[4];
    const float* qkv_b  = (const float*)d_in[5];
    const float* proj_w = (const float*)d_in[6];
    const float* proj_b = (const float*)d_in[7];
    const float* ln2_g  = (const float*)d_in[8];
    const float* ln2_b  = (const float*)d_in[9];
    const float* w1     = (const float*)d_in[10];
    const float* b1     = (const float*)d_in[11];
    const float* w2     = (const float*)d_in[12];
    const float* b2     = (const float*)d_in[13];
    const float* w3     = (const float*)d_in[14];
    const float* b3     = (const float*)d_in[15];
    float* out = (float*)d_out;

    __half *h_buf, *qkv_buf, *attn_buf, *x1_buf, *hid_buf, *wh;
    cudaGetSymbolAddress((void**)&h_buf, g_h);
    cudaGetSymbolAddress((void**)&qkv_buf, g_qkv);
    cudaGetSymbolAddress((void**)&attn_buf, g_attn);
    cudaGetSymbolAddress((void**)&x1_buf, g_x1);
    cudaGetSymbolAddress((void**)&hid_buf, g_hid);
    cudaGetSymbolAddress((void**)&wh, g_wh);

    cudaFuncSetAttribute(gemm_f16<0>,
                         cudaFuncAttributeMaxDynamicSharedMemorySize, HG_SMEM);
    cudaFuncSetAttribute(gemm_f16<1>,
                         cudaFuncAttributeMaxDynamicSharedMemorySize, HG_SMEM);
    cudaFuncSetAttribute(gemm_f16<2>,
                         cudaFuncAttributeMaxDynamicSharedMemorySize, HG_SMEM);
    cudaFuncSetAttribute(gemm_f16<3>,
                         cudaFuncAttributeMaxDynamicSharedMemorySize, HG_SMEM);
    cudaFuncSetAttribute(flash_f16_kernel,
                         cudaFuncAttributeMaxDynamicSharedMemorySize, FA_SMEM);

    const int mblocks = (MM + 127) / 128;   // 86

    // 0) weights -> fp16
    conv_h(qkv_w,  wh + WH_QKV,  C3 * CC);
    conv_h(proj_w, wh + WH_PROJ, CC * CC);
    conv_h(w1,     wh + WH_W1,   HID * CC);
    conv_h(w2,     wh + WH_W2,   HID * CC);
    conv_h(w3,     wh + WH_W3,   CC * HID);

    // 1) LN1 -> fp16
    ln_kernel<<<MM, 256>>>(x, ln1_g, ln1_b, h_buf);

    // 2) QKV GEMM -> fp16
    gemm_f16<3><<<dim3(C3 / 128, mblocks), 256, HG_SMEM>>>(
        h_buf, wh + WH_QKV, qkv_b, nullptr, qkv_buf, MM, C3, CC);

    // 3) RoPE in place (fp16)
    rope_kernel<<<MM, 256>>>(qkv_buf, freqs);

    // 4) Flash attention v2 (BQ=128) -> fp16
    {
        dim3 grid((NN + 127) / 128, BB * HH);   // (11, 96)
        flash_f16_kernel<<<grid, 256, FA_SMEM>>>(qkv_buf, attn_buf);
    }

    // 5) proj GEMM + residual(x) -> out (fp32)
    gemm_f16<1><<<dim3(CC / 128, mblocks), 256, HG_SMEM>>>(
        attn_buf, wh + WH_PROJ, proj_b, x, out, MM, CC, CC);

    // 6) LN2 -> fp16
    ln_kernel<<<MM, 256>>>(out, ln2_g, ln2_b, h_buf);

    // 7) x1 GEMM -> fp16
    gemm_f16<3><<<dim3(HID / 128, mblocks), 256, HG_SMEM>>>(
        h_buf, wh + WH_W1, b1, nullptr, x1_buf, MM, HID, CC);

    // 8) x2 GEMM with fused SwiGLU (reads fp16 x1) -> hid (fp16)
    gemm_f16<2><<<dim3(HID / 128, mblocks), 256, HG_SMEM>>>(
        h_buf, wh + WH_W2, b2, x1_buf, hid_buf, MM, HID, CC);

    // 9) mlp GEMM + residual -> out (fp32)
    gemm_f16<1><<<dim3(CC / 128, mblocks), 256, HG_SMEM>>>(
        hid_buf, wh + WH_W3, b3, out, out, MM, CC, HID);
}